// round 6
// baseline (speedup 1.0000x reference)
#include <cuda_runtime.h>
#include <cuda_bf16.h>
#include <cstdint>
#include <math.h>

// ---------------------------------------------------------------------------
// Actor_Critic — bf16x2 split-precision MMA, 512-thread GEMM CTAs,
// 3-stage cp.async pipeline, fused prep kernels.
// ---------------------------------------------------------------------------

constexpr size_t S_B = 32768;

// fp32 scratch
constexpr size_t F_TAB   = 0;
constexpr size_t F_PRE2  = 1024;
constexpr size_t F_GATES = 8192;
constexpr size_t F_MLP   = F_GATES + S_B * 1024;
constexpr size_t F_QOUT  = F_MLP   + S_B * 512;
constexpr size_t F_POL2  = F_QOUT  + S_B * 256;
constexpr size_t F_VAL2  = F_POL2  + S_B * 64;
constexpr size_t F_END   = F_VAL2  + S_B * 32;
__device__ float g_f32[F_END];

// bf16 scratch: hi at OFF, lo at OFF + B_HALF
constexpr size_t B_WIH  = 0;
constexpr size_t B_WHH  = B_WIH  + 1024 * 256;
constexpr size_t B_WBA  = B_WHH  + 1024 * 256;
constexpr size_t B_WQ   = B_WBA  + 512 * 512;
constexpr size_t B_WK   = B_WQ   + 256 * 256;
constexpr size_t B_WAT  = B_WK   + 256 * 256;
constexpr size_t B_WP1  = B_WAT  + 256 * 512;
constexpr size_t B_WP2  = B_WP1  + 128 * 256;
constexpr size_t B_WV1  = B_WP2  + 64 * 128;
constexpr size_t B_WV2  = B_WV1  + 64 * 256;      // padded 64 rows
constexpr size_t B_FUS  = B_WV2  + 64 * 64;
constexpr size_t B_HXI  = B_FUS  + S_B * 256;
constexpr size_t B_QRY  = B_HXI  + S_B * 256;
constexpr size_t B_HXO  = B_QRY  + S_B * 256;
constexpr size_t B_MLP  = B_HXO  + S_B * 256;
constexpr size_t B_AVEC = B_MLP  + S_B * 512;
constexpr size_t B_ATT  = B_AVEC + S_B * 256;
constexpr size_t B_POL1 = B_ATT  + S_B * 256;
constexpr size_t B_VAL1 = B_POL1 + S_B * 128;
constexpr size_t B_HALF = B_VAL1 + S_B * 64;
__device__ __nv_bfloat16 g_bf[2 * B_HALF];

__device__ __forceinline__ float sigmoidf_(float x) { return 1.f / (1.f + expf(-x)); }
__device__ __forceinline__ void bsplit(float v, __nv_bfloat16& h, __nv_bfloat16& l) {
    h = __float2bfloat16(v);
    l = __float2bfloat16(v - __bfloat162float(h));
}
__device__ __forceinline__ uint32_t pack2(__nv_bfloat16 a, __nv_bfloat16 b) {
    return (uint32_t)__bfloat16_as_ushort(a) | ((uint32_t)__bfloat16_as_ushort(b) << 16);
}

// ---------------------------------------------------------------------------
// K0: gated_att table (4x256) + pre2 table (4x1024)
// ---------------------------------------------------------------------------
__global__ void k0_tables(const float* __restrict__ emb,  const float* __restrict__ w_ta,
                          const float* __restrict__ b_ta, const float* __restrict__ w_ih,
                          const float* __restrict__ b_ih, const float* __restrict__ b_hh,
                          float* __restrict__ tab, float* __restrict__ pre2) {
    int t = threadIdx.x;  // 1024
    {
        int r = t >> 8, j = t & 255;
        float s = b_ta[j];
        #pragma unroll
        for (int k = 0; k < 25; k++) s += emb[r * 25 + k] * w_ta[j * 25 + k];
        tab[t] = sigmoidf_(s);
    }
    __syncthreads();
    {
        int j = t;
        const float* wrow = &w_ih[(size_t)j * 512 + 256];
        float base = b_ih[j] + b_hh[j];
        for (int r = 0; r < 4; r++) {
            const float* tr = &tab[r * 256];
            float s = base;
            for (int k = 0; k < 256; k++) s += tr[k] * wrow[k];
            pre2[r * 1024 + j] = s;
        }
    }
}

// ---------------------------------------------------------------------------
// fused weight split: 10 segments in one launch
// ---------------------------------------------------------------------------
struct WSeg { const float* src; int srcld, cols, rows, total; long long dstoff; };
struct WAll { WSeg s[10]; };

__global__ void k_wsplit_all(WAll d, __nv_bfloat16* __restrict__ hbase,
                             __nv_bfloat16* __restrict__ lbase) {
    int i = blockIdx.x * blockDim.x + threadIdx.x;
    #pragma unroll
    for (int s = 0; s < 10; s++) {
        if (i < d.s[s].total) {
            int r = i / d.s[s].cols, c = i - r * d.s[s].cols;
            float v = (r < d.s[s].rows) ? d.s[s].src[(size_t)r * d.s[s].srcld + c] : 0.f;
            __nv_bfloat16 hh, ll;
            bsplit(v, hh, ll);
            hbase[d.s[s].dstoff + i] = hh;
            lbase[d.s[s].dstoff + i] = ll;
            return;
        }
        i -= d.s[s].total;
    }
}

// ---------------------------------------------------------------------------
// fused prep: region 0 fusion(img*tab[idx]); region 1 split hx_in; region 2 split query
// nq = B*64 quads per region
// ---------------------------------------------------------------------------
__global__ void k_prep(const float4* __restrict__ img, const int* __restrict__ idx,
                       const float* __restrict__ tab,
                       const float4* __restrict__ hx_in, const float4* __restrict__ query,
                       __nv_bfloat16* __restrict__ fush, __nv_bfloat16* __restrict__ fusl,
                       __nv_bfloat16* __restrict__ hxh,  __nv_bfloat16* __restrict__ hxl,
                       __nv_bfloat16* __restrict__ qh,   __nv_bfloat16* __restrict__ ql,
                       int nq) {
    int i = blockIdx.x * blockDim.x + threadIdx.x;
    int reg = 0;
    if (i >= nq) { i -= nq; reg = 1; }
    if (i >= nq) { i -= nq; reg = 2; }
    if (i >= nq) return;
    float4 v;
    __nv_bfloat16* h;
    __nv_bfloat16* l;
    if (reg == 0) {
        int b = i >> 6, j4 = (i & 63) << 2;
        float4 g = *reinterpret_cast<const float4*>(tab + idx[b] * 256 + j4);
        v = img[i];
        v.x *= g.x; v.y *= g.y; v.z *= g.z; v.w *= g.w;
        h = fush; l = fusl;
    } else if (reg == 1) {
        v = hx_in[i]; h = hxh; l = hxl;
    } else {
        v = query[i]; h = qh; l = ql;
    }
    __nv_bfloat16 hh[4], ll[4];
    bsplit(v.x, hh[0], ll[0]); bsplit(v.y, hh[1], ll[1]);
    bsplit(v.z, hh[2], ll[2]); bsplit(v.w, hh[3], ll[3]);
    *reinterpret_cast<uint2*>(h + (size_t)i * 4) = make_uint2(pack2(hh[0], hh[1]), pack2(hh[2], hh[3]));
    *reinterpret_cast<uint2*>(l + (size_t)i * 4) = make_uint2(pack2(ll[0], ll[1]), pack2(ll[2], ll[3]));
}

// ---------------------------------------------------------------------------
// K3: LSTM activation -> hx,cx fp32 (output) + hx bf16 hi/lo
// ---------------------------------------------------------------------------
__global__ void k_lstm(const float* __restrict__ gates, const float* __restrict__ cx_in,
                       float* __restrict__ hx_out, float* __restrict__ cx_out,
                       __nv_bfloat16* __restrict__ hxh, __nv_bfloat16* __restrict__ hxl,
                       int totalq) {
    int i = blockIdx.x * blockDim.x + threadIdx.x;
    if (i >= totalq) return;
    int b = i >> 6, j = (i & 63) << 2;
    const float* g = gates + (size_t)b * 1024 + j;
    float4 gi = *reinterpret_cast<const float4*>(g);
    float4 gf = *reinterpret_cast<const float4*>(g + 256);
    float4 gg = *reinterpret_cast<const float4*>(g + 512);
    float4 go = *reinterpret_cast<const float4*>(g + 768);
    float4 c0 = *reinterpret_cast<const float4*>(cx_in + (size_t)b * 256 + j);
    float4 ho, co;
    co.x = sigmoidf_(gf.x) * c0.x + sigmoidf_(gi.x) * tanhf(gg.x); ho.x = sigmoidf_(go.x) * tanhf(co.x);
    co.y = sigmoidf_(gf.y) * c0.y + sigmoidf_(gi.y) * tanhf(gg.y); ho.y = sigmoidf_(go.y) * tanhf(co.y);
    co.z = sigmoidf_(gf.z) * c0.z + sigmoidf_(gi.z) * tanhf(gg.z); ho.z = sigmoidf_(go.z) * tanhf(co.z);
    co.w = sigmoidf_(gf.w) * c0.w + sigmoidf_(gi.w) * tanhf(gg.w); ho.w = sigmoidf_(go.w) * tanhf(co.w);
    size_t o = (size_t)b * 256 + j;
    *reinterpret_cast<float4*>(hx_out + o) = ho;
    *reinterpret_cast<float4*>(cx_out + o) = co;
    __nv_bfloat16 hh[4], ll[4];
    bsplit(ho.x, hh[0], ll[0]); bsplit(ho.y, hh[1], ll[1]);
    bsplit(ho.z, hh[2], ll[2]); bsplit(ho.w, hh[3], ll[3]);
    *reinterpret_cast<uint2*>(hxh + o) = make_uint2(pack2(hh[0], hh[1]), pack2(hh[2], hh[3]));
    *reinterpret_cast<uint2*>(hxl + o) = make_uint2(pack2(ll[0], ll[1]), pack2(ll[2], ll[3]));
}

// ---------------------------------------------------------------------------
// MMA / cp.async helpers
// ---------------------------------------------------------------------------
__device__ __forceinline__ void ldm4(uint32_t* r, uint32_t addr) {
    asm volatile("ldmatrix.sync.aligned.m8n8.x4.shared.b16 {%0,%1,%2,%3}, [%4];"
                 : "=r"(r[0]), "=r"(r[1]), "=r"(r[2]), "=r"(r[3]) : "r"(addr));
}
__device__ __forceinline__ void mma16816(float* c, const uint32_t* a, uint32_t b0, uint32_t b1) {
    asm volatile(
        "mma.sync.aligned.m16n8k16.row.col.f32.bf16.bf16.f32 "
        "{%0,%1,%2,%3}, {%4,%5,%6,%7}, {%8,%9}, {%0,%1,%2,%3};"
        : "+f"(c[0]), "+f"(c[1]), "+f"(c[2]), "+f"(c[3])
        : "r"(a[0]), "r"(a[1]), "r"(a[2]), "r"(a[3]), "r"(b0), "r"(b1));
}
#define CPA16(dst, src) asm volatile("cp.async.cg.shared.global [%0], [%1], 16;\n" :: "r"(dst), "l"(src))
#define CPCOMMIT()      asm volatile("cp.async.commit_group;\n")
#define CPWAIT2()       asm volatile("cp.async.wait_group 2;\n")
#define CPWAIT1()       asm volatile("cp.async.wait_group 1;\n")
#define CPWAIT0()       asm volatile("cp.async.wait_group 0;\n")

// ---------------------------------------------------------------------------
// Tensor-core GEMM: 512 threads, 16 warps (4m x 4n), warp tile 32 x (BN/4),
// 3-stage cp.async pipeline. bf16 hi/lo, 3 MMA passes.
// EPI 0: +bias/relu; EPI 1: +aux0[idxp[m]*1024+n]; EPI 2: relu -> tanh(aux0+v)*aux1
// OUTM bit0: fp32 C; bit1: bf16 Ch/Cl.
// ---------------------------------------------------------------------------
template <int BN, int ACT, int EPI, int OUTM>
__global__ void __launch_bounds__(512)
mma_gemm(int N,
         const __nv_bfloat16* __restrict__ A0h, const __nv_bfloat16* __restrict__ A0l, int lda0,
         const __nv_bfloat16* __restrict__ W0h, const __nv_bfloat16* __restrict__ W0l, int ldw0, int K0,
         const __nv_bfloat16* __restrict__ A1h, const __nv_bfloat16* __restrict__ A1l, int lda1,
         const __nv_bfloat16* __restrict__ W1h, const __nv_bfloat16* __restrict__ W1l, int ldw1, int K1,
         const float* __restrict__ bias, const float* __restrict__ aux0,
         const float* __restrict__ aux1, const int* __restrict__ idxp,
         float* __restrict__ C, __nv_bfloat16* __restrict__ Ch, __nv_bfloat16* __restrict__ Cl,
         int ldc) {
    constexpr int WN     = BN / 4;            // warp n-extent (4 warps in n)
    constexpr int NT8    = WN / 8;
    constexpr int N16T   = WN / 16;
    constexpr int SSTR   = 40;                // bf16 per smem row (80B, conflict-free)
    constexpr int ACH    = 128 * SSTR;        // elems per A array (hi or lo)
    constexpr int WCH    = BN * SSTR;
    constexpr int STAGEB = (2 * ACH + 2 * WCH) * 2;  // stage bytes

    extern __shared__ __nv_bfloat16 smem_dyn[];

    const int tid  = threadIdx.x;
    const int lane = tid & 31;
    const int wid  = tid >> 5;
    const int wm = wid & 3, wn = wid >> 2;    // 4 x 4 warp grid
    const int m0 = blockIdx.y * 128;
    const int n0 = blockIdx.x * BN;

    const uint32_t smb = (uint32_t)__cvta_generic_to_shared(smem_dyn);

    float acc[2][NT8][4];
    #pragma unroll
    for (int i = 0; i < 2; i++)
        #pragma unroll
        for (int j = 0; j < NT8; j++)
            #pragma unroll
            for (int q = 0; q < 4; q++) acc[i][j][q] = 0.f;

    const int nc0 = K0 >> 5;
    const int NC  = nc0 + (K1 >> 5);

    auto issue = [&](int c) {
        const __nv_bfloat16 *Ah, *Al, *Wh, *Wl;
        int lda, ldw, kc;
        if (c < nc0) { Ah = A0h; Al = A0l; Wh = W0h; Wl = W0l; lda = lda0; ldw = ldw0; kc = c << 5; }
        else         { Ah = A1h; Al = A1l; Wh = W1h; Wl = W1l; lda = lda1; ldw = ldw1; kc = (c - nc0) << 5; }
        const uint32_t sb = smb + (uint32_t)(c % 3) * STAGEB;
        {   // A: 128 rows x 4 segs = 512 slots, exactly one per thread
            int row = tid >> 2, seg = tid & 3;
            uint32_t off = (uint32_t)(row * SSTR + seg * 8) * 2;
            size_t go = (size_t)(m0 + row) * lda + kc + seg * 8;
            CPA16(sb + off, Ah + go);
            CPA16(sb + ACH * 2 + off, Al + go);
        }
        if (BN == 128) {
            int row = tid >> 2, seg = tid & 3;
            uint32_t off = (uint32_t)(row * SSTR + seg * 8) * 2;
            size_t go = (size_t)(n0 + row) * ldw + kc + seg * 8;
            CPA16(sb + ACH * 4 + off, Wh + go);
            CPA16(sb + ACH * 4 + WCH * 2 + off, Wl + go);
        } else if (tid < BN * 4) {
            int row = tid >> 2, seg = tid & 3;
            uint32_t off = (uint32_t)(row * SSTR + seg * 8) * 2;
            size_t go = (size_t)(n0 + row) * ldw + kc + seg * 8;
            CPA16(sb + ACH * 4 + off, Wh + go);
            CPA16(sb + ACH * 4 + WCH * 2 + off, Wl + go);
        }
    };

    issue(0); CPCOMMIT();
    if (NC > 1) { issue(1); CPCOMMIT(); }

    for (int c = 0; c < NC; c++) {
        if (c + 2 < NC) {
            issue(c + 2); CPCOMMIT();
            CPWAIT2();
        } else if (c + 1 < NC) {
            CPWAIT1();
        } else {
            CPWAIT0();
        }
        __syncthreads();

        const uint32_t sb  = smb + (uint32_t)(c % 3) * STAGEB;
        const uint32_t bAh = sb;
        const uint32_t bAl = sb + ACH * 2;
        const uint32_t bWh = sb + ACH * 4;
        const uint32_t bWl = sb + ACH * 4 + WCH * 2;

        #pragma unroll
        for (int kk = 0; kk < 32; kk += 16) {
            uint32_t ah[2][4], al[2][4];
            #pragma unroll
            for (int mt = 0; mt < 2; mt++) {
                int row = wm * 32 + mt * 16 + (lane & 15);
                int col = kk + ((lane >> 4) << 3);
                uint32_t off = (uint32_t)(row * SSTR + col) * 2u;
                ldm4(ah[mt], bAh + off);
                ldm4(al[mt], bAl + off);
            }
            uint32_t bh[N16T][4], bl[N16T][4];
            #pragma unroll
            for (int t = 0; t < N16T; t++) {
                int row = wn * WN + t * 16 + (lane & 15);
                int col = kk + ((lane >> 4) << 3);
                uint32_t off = (uint32_t)(row * SSTR + col) * 2u;
                ldm4(bh[t], bWh + off);
                ldm4(bl[t], bWl + off);
            }
            #pragma unroll
            for (int mt = 0; mt < 2; mt++)
                #pragma unroll
                for (int nt = 0; nt < NT8; nt++) {
                    int t = nt >> 1, hs = nt & 1;
                    mma16816(acc[mt][nt], ah[mt], bh[t][hs], bh[t][2 + hs]);
                    mma16816(acc[mt][nt], al[mt], bh[t][hs], bh[t][2 + hs]);
                    mma16816(acc[mt][nt], ah[mt], bl[t][hs], bl[t][2 + hs]);
                }
        }
        __syncthreads();
    }

    // epilogue
    #pragma unroll
    for (int mt = 0; mt < 2; mt++) {
        int r0 = m0 + wm * 32 + mt * 16 + (lane >> 2);
        int r1 = r0 + 8;
        int ib0 = 0, ib1 = 0;
        if (EPI == 1) { ib0 = idxp[r0]; ib1 = idxp[r1]; }
        #pragma unroll
        for (int nt = 0; nt < NT8; nt++) {
            int cc = n0 + wn * WN + nt * 8 + ((lane & 3) << 1);
            if (cc < N) {
                #pragma unroll
                for (int p = 0; p < 2; p++) {
                    int r  = p ? r1 : r0;
                    int ib = p ? ib1 : ib0;
                    float x = acc[mt][nt][2 * p];
                    float y = acc[mt][nt][2 * p + 1];
                    if (EPI == 1) {
                        x += aux0[(size_t)ib * 1024 + cc];
                        y += aux0[(size_t)ib * 1024 + cc + 1];
                    } else if (bias) {
                        x += bias[cc];
                        y += bias[cc + 1];
                    }
                    if (ACT) { x = fmaxf(x, 0.f); y = fmaxf(y, 0.f); }
                    if (EPI == 2) {
                        x = tanhf(aux0[(size_t)r * 256 + cc] + x)     * aux1[(size_t)r * 512 + 256 + cc];
                        y = tanhf(aux0[(size_t)r * 256 + cc + 1] + y) * aux1[(size_t)r * 512 + 256 + cc + 1];
                    }
                    size_t o = (size_t)r * ldc + cc;
                    if (OUTM & 1)
                        *reinterpret_cast<float2*>(&C[o]) = make_float2(x, y);
                    if (OUTM & 2) {
                        __nv_bfloat16 xh, xl, yh, yl;
                        bsplit(x, xh, xl);
                        bsplit(y, yh, yl);
                        *reinterpret_cast<uint32_t*>(Ch + o) = pack2(xh, yh);
                        *reinterpret_cast<uint32_t*>(Cl + o) = pack2(xl, yl);
                    }
                }
            }
        }
    }
}

// ---------------------------------------------------------------------------
// Final heads
// ---------------------------------------------------------------------------
__global__ void k_heads(const float* __restrict__ pol2, const float* __restrict__ val2,
                        const float* __restrict__ w_p, const float* __restrict__ b_p,
                        const float* __restrict__ w_v, const float* __restrict__ b_v,
                        float* __restrict__ out_val, float* __restrict__ out_pol) {
    __shared__ float sp[64][65];
    __shared__ float sv[64][33];
    int r0 = blockIdx.x * 64;
    for (int i = threadIdx.x; i < 64 * 64; i += blockDim.x)
        sp[i >> 6][i & 63] = pol2[(size_t)r0 * 64 + i];
    for (int i = threadIdx.x; i < 64 * 32; i += blockDim.x)
        sv[i >> 5][i & 31] = val2[(size_t)r0 * 32 + i];
    __syncthreads();
    int t = threadIdx.x;
    if (t < 64) {
        int b = r0 + t;
        float p0 = b_p[0], p1 = b_p[1], p2 = b_p[2];
        #pragma unroll
        for (int k = 0; k < 64; k++) {
            float x = sp[t][k];
            p0 = fmaf(x, w_p[k], p0);
            p1 = fmaf(x, w_p[64 + k], p1);
            p2 = fmaf(x, w_p[128 + k], p2);
        }
        out_pol[(size_t)b * 3 + 0] = p0;
        out_pol[(size_t)b * 3 + 1] = p1;
        out_pol[(size_t)b * 3 + 2] = p2;
        float v = b_v[0];
        #pragma unroll
        for (int k = 0; k < 32; k++) v = fmaf(sv[t][k], w_v[k], v);
        out_val[b] = v;
    }
}

// ---------------------------------------------------------------------------
// host launcher
// ---------------------------------------------------------------------------
extern "C" void kernel_launch(void* const* d_in, const int* in_sizes, int n_in,
                              void* d_out, int out_size) {
    const float* img   = (const float*)d_in[0];
    const int*   idx   = (const int*)  d_in[1];
    const float* hx_in = (const float*)d_in[2];
    const float* cx_in = (const float*)d_in[3];
    const float* query = (const float*)d_in[4];
    const float* emb   = (const float*)d_in[5];
    const float* w_ta  = (const float*)d_in[6];
    const float* b_ta  = (const float*)d_in[7];
    const float* w_ih  = (const float*)d_in[8];
    const float* w_hh  = (const float*)d_in[9];
    const float* b_ih  = (const float*)d_in[10];
    const float* b_hh  = (const float*)d_in[11];
    const float* w_q   = (const float*)d_in[12];
    const float* b_q   = (const float*)d_in[13];
    const float* w_k   = (const float*)d_in[14];
    const float* b_k   = (const float*)d_in[15];
    const float* w_ba  = (const float*)d_in[16];
    const float* b_ba  = (const float*)d_in[17];
    const float* w_at  = (const float*)d_in[18];
    const float* b_at  = (const float*)d_in[19];
    const float* w_p1  = (const float*)d_in[20];
    const float* b_p1  = (const float*)d_in[21];
    const float* w_p2  = (const float*)d_in[22];
    const float* b_p2  = (const float*)d_in[23];
    const float* w_p   = (const float*)d_in[24];
    const float* b_p   = (const float*)d_in[25];
    const float* w_v1  = (const float*)d_in[26];
    const float* b_v1  = (const float*)d_in[27];
    const float* w_v2  = (const float*)d_in[28];
    const float* b_v2  = (const float*)d_in[29];
    const float* w_v   = (const float*)d_in[30];
    const float* b_v   = (const float*)d_in[31];

    const int B = in_sizes[0] / 256;  // 32768

    float* F = nullptr;
    cudaGetSymbolAddress((void**)&F, g_f32);
    __nv_bfloat16* BF = nullptr;
    cudaGetSymbolAddress((void**)&BF, g_bf);

    float* tab   = F + F_TAB;
    float* pre2  = F + F_PRE2;
    float* gates = F + F_GATES;
    float* mlpf  = F + F_MLP;
    float* qout  = F + F_QOUT;
    float* pol2  = F + F_POL2;
    float* val2  = F + F_VAL2;

    auto HI = [&](size_t o) { return BF + o; };
    auto LO = [&](size_t o) { return BF + o + B_HALF; };

    float* out   = (float*)d_out;
    float* o_val = out;
    float* o_pol = out + (size_t)B;
    float* o_hx  = out + (size_t)B * 4;
    float* o_cx  = o_hx + (size_t)B * 256;

    // smem: 3 stages
    const int SM128 = ((2 * 128 * 40 + 2 * 128 * 40) * 2) * 3;  // 122880
    const int SM64  = ((2 * 128 * 40 + 2 * 64 * 40) * 2) * 3;   // 92160
    cudaFuncSetAttribute(mma_gemm<128, 0, 1, 1>, cudaFuncAttributeMaxDynamicSharedMemorySize, SM128);
    cudaFuncSetAttribute(mma_gemm<128, 1, 0, 3>, cudaFuncAttributeMaxDynamicSharedMemorySize, SM128);
    cudaFuncSetAttribute(mma_gemm<128, 1, 0, 1>, cudaFuncAttributeMaxDynamicSharedMemorySize, SM128);
    cudaFuncSetAttribute(mma_gemm<128, 1, 2, 2>, cudaFuncAttributeMaxDynamicSharedMemorySize, SM128);
    cudaFuncSetAttribute(mma_gemm<128, 1, 0, 2>, cudaFuncAttributeMaxDynamicSharedMemorySize, SM128);
    cudaFuncSetAttribute(mma_gemm<64, 1, 0, 1>,  cudaFuncAttributeMaxDynamicSharedMemorySize, SM64);
    cudaFuncSetAttribute(mma_gemm<64, 1, 0, 2>,  cudaFuncAttributeMaxDynamicSharedMemorySize, SM64);

    // K0: tables
    k0_tables<<<1, 1024>>>(emb, w_ta, b_ta, w_ih, b_ih, b_hh, tab, pre2);

    // fused weight split
    {
        WAll d;
        auto seg = [&](int i, const float* src, int srcld, int cols, int rows, int padrows, size_t off) {
            d.s[i] = WSeg{src, srcld, cols, rows, padrows * cols, (long long)off};
        };
        seg(0, w_ih, 512, 256, 1024, 1024, B_WIH);
        seg(1, w_hh, 256, 256, 1024, 1024, B_WHH);
        seg(2, w_ba, 512, 512, 512, 512, B_WBA);
        seg(3, w_q,  256, 256, 256, 256, B_WQ);
        seg(4, w_k,  256, 256, 256, 256, B_WK);
        seg(5, w_at, 512, 512, 256, 256, B_WAT);
        seg(6, w_p1, 256, 256, 128, 128, B_WP1);
        seg(7, w_p2, 128, 128, 64, 64, B_WP2);
        seg(8, w_v1, 256, 256, 64, 64, B_WV1);
        seg(9, w_v2, 64, 64, 32, 64, B_WV2);
        int total = 0;
        for (int i = 0; i < 10; i++) total += d.s[i].total;
        k_wsplit_all<<<(total + 255) / 256, 256>>>(d, BF, BF + B_HALF);
    }

    // fused prep: fusion + hx split + query split
    k_prep<<<(3 * B * 64 + 255) / 256, 256>>>(
        (const float4*)img, idx, tab, (const float4*)hx_in, (const float4*)query,
        HI(B_FUS), LO(B_FUS), HI(B_HXI), LO(B_HXI), HI(B_QRY), LO(B_QRY), B * 64);

    // K2: gates = fus @ w_ih[:,:256]^T + hx @ w_hh^T + pre2[idx]
    mma_gemm<128, 0, 1, 1><<<dim3(8, B / 128), 512, SM128>>>(
        1024,
        HI(B_FUS), LO(B_FUS), 256, HI(B_WIH), LO(B_WIH), 256, 256,
        HI(B_HXI), LO(B_HXI), 256, HI(B_WHH), LO(B_WHH), 256, 256,
        nullptr, pre2, nullptr, idx, gates, nullptr, nullptr, 1024);

    // K3: LSTM
    k_lstm<<<(B * 64 + 255) / 256, 256>>>(gates, cx_in, o_hx, o_cx, HI(B_HXO), LO(B_HXO), B * 64);

    // K5: qout = relu(query @ w_q^T + b_q)
    mma_gemm<128, 1, 0, 1><<<dim3(2, B / 128), 512, SM128>>>(
        256,
        HI(B_QRY), LO(B_QRY), 256, HI(B_WQ), LO(B_WQ), 256, 256,
        nullptr, nullptr, 0, nullptr, nullptr, 0, 0,
        b_q, nullptr, nullptr, nullptr, qout, nullptr, nullptr, 256);

    // K4: mlp = relu([fus|hx] @ w_ba^T + b_ba)
    mma_gemm<128, 1, 0, 3><<<dim3(4, B / 128), 512, SM128>>>(
        512,
        HI(B_FUS), LO(B_FUS), 256, HI(B_WBA), LO(B_WBA), 512, 256,
        HI(B_HXO), LO(B_HXO), 256, HI(B_WBA) + 256, LO(B_WBA) + 256, 512, 256,
        b_ba, nullptr, nullptr, nullptr, mlpf, HI(B_MLP), LO(B_MLP), 512);

    // K6: avec = tanh(qout + relu(key @ w_k^T + b_k)) * val
    mma_gemm<128, 1, 2, 2><<<dim3(2, B / 128), 512, SM128>>>(
        256,
        HI(B_MLP), LO(B_MLP), 512, HI(B_WK), LO(B_WK), 256, 256,
        nullptr, nullptr, 0, nullptr, nullptr, 0, 0,
        b_k, qout, mlpf, nullptr, nullptr, HI(B_AVEC), LO(B_AVEC), 256);

    // K7: attnw = relu([avec|hx] @ w_at^T + b_at)
    mma_gemm<128, 1, 0, 2><<<dim3(2, B / 128), 512, SM128>>>(
        256,
        HI(B_AVEC), LO(B_AVEC), 256, HI(B_WAT), LO(B_WAT), 512, 256,
        HI(B_HXO), LO(B_HXO), 256, HI(B_WAT) + 256, LO(B_WAT) + 256, 512, 256,
        b_at, nullptr, nullptr, nullptr, nullptr, HI(B_ATT), LO(B_ATT), 256);

    // K8: pol1 = relu(attnw @ w_p1^T + b_p1)
    mma_gemm<128, 1, 0, 2><<<dim3(1, B / 128), 512, SM128>>>(
        128,
        HI(B_ATT), LO(B_ATT), 256, HI(B_WP1), LO(B_WP1), 256, 256,
        nullptr, nullptr, 0, nullptr, nullptr, 0, 0,
        b_p1, nullptr, nullptr, nullptr, nullptr, HI(B_POL1), LO(B_POL1), 128);

    // K9: pol2 = relu(pol1 @ w_p2^T + b_p2)
    mma_gemm<64, 1, 0, 1><<<dim3(1, B / 128), 512, SM64>>>(
        64,
        HI(B_POL1), LO(B_POL1), 128, HI(B_WP2), LO(B_WP2), 128, 128,
        nullptr, nullptr, 0, nullptr, nullptr, 0, 0,
        b_p2, nullptr, nullptr, nullptr, pol2, nullptr, nullptr, 64);

    // K10: val1 = relu(attnw @ w_v1^T + b_v1)
    mma_gemm<64, 1, 0, 2><<<dim3(1, B / 128), 512, SM64>>>(
        64,
        HI(B_ATT), LO(B_ATT), 256, HI(B_WV1), LO(B_WV1), 256, 256,
        nullptr, nullptr, 0, nullptr, nullptr, 0, 0,
        b_v1, nullptr, nullptr, nullptr, nullptr, HI(B_VAL1), LO(B_VAL1), 64);

    // K11: val2 = relu(val1 @ w_v2^T + b_v2)   (ldc=32)
    mma_gemm<64, 1, 0, 1><<<dim3(1, B / 128), 512, SM64>>>(
        32,
        HI(B_VAL1), LO(B_VAL1), 64, HI(B_WV2), LO(B_WV2), 64, 64,
        nullptr, nullptr, 0, nullptr, nullptr, 0, 0,
        b_v2, nullptr, nullptr, nullptr, val2, nullptr, nullptr, 32);

    // K12: heads
    k_heads<<<B / 64, 256>>>(pol2, val2, w_p, b_p, w_v, b_v, o_val, o_pol);
}

// round 7
// speedup vs baseline: 1.3360x; 1.3360x over previous
#include <cuda_runtime.h>
#include <cuda_fp16.h>
#include <cstdint>
#include <math.h>

// ---------------------------------------------------------------------------
// Actor_Critic — fp16 2-pass split-precision MMA.
//   weights: w = wh + wl (two fp16, preprocessed once)
//   activations: single fp16 rounding
//   product: a*w ~= ar*wh + ar*wl  (error ~ (a-ar)*w ~ 2^-12 relative)
// 256-thread GEMM CTAs, 3-stage cp.async, 2 CTAs/SM.
// ---------------------------------------------------------------------------

constexpr size_t S_B = 32768;

// fp32 scratch
constexpr size_t F_TAB   = 0;
constexpr size_t F_PRE2  = 1024;
constexpr size_t F_GATES = 8192;
constexpr size_t F_MLP   = F_GATES + S_B * 1024;
constexpr size_t F_QOUT  = F_MLP   + S_B * 512;
constexpr size_t F_PV2   = F_QOUT  + S_B * 256;      // [B,96]: pol2 0:64 | val2 64:96
constexpr size_t F_END   = F_PV2   + S_B * 96;
__device__ float g_f32[F_END];

// fp16 scratch (halves)
constexpr size_t H_WIH_H   = 0;                       // 1024x256
constexpr size_t H_WIH_L   = H_WIH_H   + 262144;
constexpr size_t H_WHH_H   = H_WIH_L   + 262144;      // 1024x256
constexpr size_t H_WHH_L   = H_WHH_H   + 262144;
constexpr size_t H_WBA_H   = H_WHH_L   + 262144;      // 512x512
constexpr size_t H_WBA_L   = H_WBA_H   + 262144;
constexpr size_t H_WQ_H    = H_WBA_L   + 262144;      // 256x256
constexpr size_t H_WQ_L    = H_WQ_H    + 65536;
constexpr size_t H_WK_H    = H_WQ_L    + 65536;       // 256x256
constexpr size_t H_WK_L    = H_WK_H    + 65536;
constexpr size_t H_WAT_H   = H_WK_L    + 65536;       // 256x512
constexpr size_t H_WAT_L   = H_WAT_H   + 131072;
constexpr size_t H_WPV_H   = H_WAT_L   + 131072;      // 192x256 = w_p1 rows 0:128, w_v1 128:192
constexpr size_t H_WPV_L   = H_WPV_H   + 49152;
constexpr size_t H_WC_H    = H_WPV_L   + 49152;       // 128x192 block-diag [wp2|0 ; 0|wv2], rows 96:128 zero
constexpr size_t H_WC_L    = H_WC_H    + 24576;
constexpr size_t H_FUS     = H_WC_L    + 24576;       // B*256
constexpr size_t H_HXI     = H_FUS     + S_B * 256;
constexpr size_t H_QRY     = H_HXI     + S_B * 256;
constexpr size_t H_HXO     = H_QRY     + S_B * 256;
constexpr size_t H_MLP     = H_HXO     + S_B * 256;   // B*512
constexpr size_t H_AVEC    = H_MLP     + S_B * 512;
constexpr size_t H_ATT     = H_AVEC    + S_B * 256;
constexpr size_t H_P1V1    = H_ATT     + S_B * 256;   // B*192 (pol1 0:128 | val1 128:192)
constexpr size_t H_END     = H_P1V1    + S_B * 192;
__device__ __half g_hf[H_END];

__device__ __forceinline__ float sigmoidf_(float x) { return 1.f / (1.f + expf(-x)); }
__device__ __forceinline__ uint32_t pack2h(__half a, __half b) {
    return (uint32_t)__half_as_ushort(a) | ((uint32_t)__half_as_ushort(b) << 16);
}

// ---------------------------------------------------------------------------
// K0: gated_att table (4x256) + pre2 table (4x1024)
// ---------------------------------------------------------------------------
__global__ void k0_tables(const float* __restrict__ emb,  const float* __restrict__ w_ta,
                          const float* __restrict__ b_ta, const float* __restrict__ w_ih,
                          const float* __restrict__ b_ih, const float* __restrict__ b_hh,
                          float* __restrict__ tab, float* __restrict__ pre2) {
    int t = threadIdx.x;  // 1024
    {
        int r = t >> 8, j = t & 255;
        float s = b_ta[j];
        #pragma unroll
        for (int k = 0; k < 25; k++) s += emb[r * 25 + k] * w_ta[j * 25 + k];
        tab[t] = sigmoidf_(s);
    }
    __syncthreads();
    {
        int j = t;
        const float* wrow = &w_ih[(size_t)j * 512 + 256];
        float base = b_ih[j] + b_hh[j];
        for (int r = 0; r < 4; r++) {
            const float* tr = &tab[r * 256];
            float s = base;
            for (int k = 0; k < 256; k++) s += tr[k] * wrow[k];
            pre2[r * 1024 + j] = s;
        }
    }
}

// ---------------------------------------------------------------------------
// fused weight split into fp16 hi/lo. mode 0: normal; mode 2: p2/v2 block-diag.
// ---------------------------------------------------------------------------
struct WSeg { const float* src; const float* src2; int srcld, cols, rows, total, mode;
              long long hoff, loff; };
struct WAll { WSeg s[9]; };

__global__ void k_wsplit_all(WAll d, __half* __restrict__ base) {
    int i = blockIdx.x * blockDim.x + threadIdx.x;
    #pragma unroll
    for (int s = 0; s < 9; s++) {
        const WSeg& g = d.s[s];
        if (i < g.total) {
            float v;
            if (g.mode == 0) {
                int r = i / g.cols, c = i - r * g.cols;
                v = (r < g.rows) ? g.src[(size_t)r * g.srcld + c] : 0.f;
            } else {
                int r = i / 192, c = i - r * 192;
                if (r < 64)       v = (c < 128) ? g.src[r * 128 + c] : 0.f;
                else if (c >= 128 && r - 64 < 32) v = g.src2[(r - 64) * 64 + (c - 128)];
                else              v = 0.f;
            }
            __half h = __float2half(v);
            __half l = __float2half(v - __half2float(h));
            base[g.hoff + i] = h;
            base[g.loff + i] = l;
            return;
        }
        i -= g.total;
    }
}

// ---------------------------------------------------------------------------
// fused prep: region 0 fusion(img*tab[idx]); 1: round hx_in; 2: round query
// ---------------------------------------------------------------------------
__global__ void k_prep(const float4* __restrict__ img, const int* __restrict__ idx,
                       const float* __restrict__ tab,
                       const float4* __restrict__ hx_in, const float4* __restrict__ query,
                       __half* __restrict__ fus, __half* __restrict__ hxi,
                       __half* __restrict__ qry, int nq) {
    int i = blockIdx.x * blockDim.x + threadIdx.x;
    int reg = 0;
    if (i >= nq) { i -= nq; reg = 1; }
    if (i >= nq) { i -= nq; reg = 2; }
    if (i >= nq) return;
    float4 v;
    __half* dst;
    if (reg == 0) {
        int b = i >> 6, j4 = (i & 63) << 2;
        float4 g = *reinterpret_cast<const float4*>(tab + idx[b] * 256 + j4);
        v = img[i];
        v.x *= g.x; v.y *= g.y; v.z *= g.z; v.w *= g.w;
        dst = fus;
    } else if (reg == 1) { v = hx_in[i]; dst = hxi; }
    else                 { v = query[i]; dst = qry; }
    uint2 u = make_uint2(pack2h(__float2half(v.x), __float2half(v.y)),
                         pack2h(__float2half(v.z), __float2half(v.w)));
    *reinterpret_cast<uint2*>(dst + (size_t)i * 4) = u;
}

// ---------------------------------------------------------------------------
// K3: LSTM -> hx,cx fp32 (outputs) + hx fp16
// ---------------------------------------------------------------------------
__global__ void k_lstm(const float* __restrict__ gates, const float* __restrict__ cx_in,
                       float* __restrict__ hx_out, float* __restrict__ cx_out,
                       __half* __restrict__ hxo, int totalq) {
    int i = blockIdx.x * blockDim.x + threadIdx.x;
    if (i >= totalq) return;
    int b = i >> 6, j = (i & 63) << 2;
    const float* g = gates + (size_t)b * 1024 + j;
    float4 gi = *reinterpret_cast<const float4*>(g);
    float4 gf = *reinterpret_cast<const float4*>(g + 256);
    float4 gg = *reinterpret_cast<const float4*>(g + 512);
    float4 go = *reinterpret_cast<const float4*>(g + 768);
    float4 c0 = *reinterpret_cast<const float4*>(cx_in + (size_t)b * 256 + j);
    float4 ho, co;
    co.x = sigmoidf_(gf.x) * c0.x + sigmoidf_(gi.x) * tanhf(gg.x); ho.x = sigmoidf_(go.x) * tanhf(co.x);
    co.y = sigmoidf_(gf.y) * c0.y + sigmoidf_(gi.y) * tanhf(gg.y); ho.y = sigmoidf_(go.y) * tanhf(co.y);
    co.z = sigmoidf_(gf.z) * c0.z + sigmoidf_(gi.z) * tanhf(gg.z); ho.z = sigmoidf_(go.z) * tanhf(co.z);
    co.w = sigmoidf_(gf.w) * c0.w + sigmoidf_(gi.w) * tanhf(gg.w); ho.w = sigmoidf_(go.w) * tanhf(co.w);
    size_t o = (size_t)b * 256 + j;
    *reinterpret_cast<float4*>(hx_out + o) = ho;
    *reinterpret_cast<float4*>(cx_out + o) = co;
    uint2 u = make_uint2(pack2h(__float2half(ho.x), __float2half(ho.y)),
                         pack2h(__float2half(ho.z), __float2half(ho.w)));
    *reinterpret_cast<uint2*>(hxo + o) = u;
}

// ---------------------------------------------------------------------------
// MMA / cp.async helpers
// ---------------------------------------------------------------------------
__device__ __forceinline__ void ldm4(uint32_t* r, uint32_t addr) {
    asm volatile("ldmatrix.sync.aligned.m8n8.x4.shared.b16 {%0,%1,%2,%3}, [%4];"
                 : "=r"(r[0]), "=r"(r[1]), "=r"(r[2]), "=r"(r[3]) : "r"(addr));
}
__device__ __forceinline__ void mma16816(float* c, const uint32_t* a, uint32_t b0, uint32_t b1) {
    asm volatile(
        "mma.sync.aligned.m16n8k16.row.col.f32.f16.f16.f32 "
        "{%0,%1,%2,%3}, {%4,%5,%6,%7}, {%8,%9}, {%0,%1,%2,%3};"
        : "+f"(c[0]), "+f"(c[1]), "+f"(c[2]), "+f"(c[3])
        : "r"(a[0]), "r"(a[1]), "r"(a[2]), "r"(a[3]), "r"(b0), "r"(b1));
}
#define CPA16(dst, src) asm volatile("cp.async.cg.shared.global [%0], [%1], 16;\n" :: "r"(dst), "l"(src))
#define CPCOMMIT()      asm volatile("cp.async.commit_group;\n")
#define CPWAIT2()       asm volatile("cp.async.wait_group 2;\n")
#define CPWAIT1()       asm volatile("cp.async.wait_group 1;\n")
#define CPWAIT0()       asm volatile("cp.async.wait_group 0;\n")

// ---------------------------------------------------------------------------
// GEMM: C = epi( sum_seg A_seg @ W_seg^T ), A fp16, W fp16 hi+lo (2 MMA passes)
// 256 threads, 8 warps (4m x 2n), BM=128, 3-stage cp.async, 2 CTAs/SM.
// EPI 0: +bias (split at nsplit into bias/bias2), relu if ACT
// EPI 1: +aux0[idxp[m]*1024+n]
// EPI 2: (+bias, relu) -> tanh(aux0[m*256+n]+v) * aux1[m*512+256+n]
// OUTM bit0: fp32 C; bit1: fp16 Ch.
// ---------------------------------------------------------------------------
template <int BN, int ACT, int EPI, int OUTM>
__global__ void __launch_bounds__(256, 2)
mma_gemm(int N,
         const __half* __restrict__ A0, int lda0,
         const __half* __restrict__ W0h, const __half* __restrict__ W0l, int ldw0, int K0,
         const __half* __restrict__ A1, int lda1,
         const __half* __restrict__ W1h, const __half* __restrict__ W1l, int ldw1, int K1,
         const float* __restrict__ bias, const float* __restrict__ bias2, int nsplit,
         const float* __restrict__ aux0, const float* __restrict__ aux1,
         const int* __restrict__ idxp,
         float* __restrict__ C, __half* __restrict__ Ch, int ldc) {
    constexpr int WN      = BN / 2;                 // warp n-extent (2 warps in n)
    constexpr int NT8     = WN / 8;
    constexpr int N16T    = WN / 16;
    constexpr int SSTR    = 40;                     // halves per smem row (80B, conflict-free)
    constexpr int A_BYTES = 128 * SSTR * 2;         // 10240
    constexpr int W_BYTES = BN * SSTR * 2;
    constexpr int STAGEB  = A_BYTES + 2 * W_BYTES;
    constexpr int WIT     = BN / 64;                // W cp.async iters (slots = BN*4)

    extern __shared__ __half smem_dyn[];

    const int tid  = threadIdx.x;
    const int lane = tid & 31;
    const int wid  = tid >> 5;
    const int wm = wid & 3, wn = wid >> 2;          // 4 x 2 warps
    const int m0 = blockIdx.y * 128;
    const int n0 = blockIdx.x * BN;

    const uint32_t smb = (uint32_t)__cvta_generic_to_shared(smem_dyn);

    float acc[2][NT8][4];
    #pragma unroll
    for (int i = 0; i < 2; i++)
        #pragma unroll
        for (int j = 0; j < NT8; j++)
            #pragma unroll
            for (int q = 0; q < 4; q++) acc[i][j][q] = 0.f;

    const int nc0 = K0 >> 5;
    const int NC  = nc0 + (K1 >> 5);

    auto issue = [&](int c) {
        const __half *A, *Wh, *Wl;
        int lda, ldw, kc;
        if (c < nc0) { A = A0; Wh = W0h; Wl = W0l; lda = lda0; ldw = ldw0; kc = c << 5; }
        else         { A = A1; Wh = W1h; Wl = W1l; lda = lda1; ldw = ldw1; kc = (c - nc0) << 5; }
        const uint32_t sb = smb + (uint32_t)(c % 3) * STAGEB;
        #pragma unroll
        for (int it = 0; it < 2; it++) {            // A: 128 rows x 4 segs
            int idx = tid + it * 256;
            int row = idx >> 2, seg = idx & 3;
            uint32_t off = (uint32_t)(row * SSTR + seg * 8) * 2;
            CPA16(sb + off, A + (size_t)(m0 + row) * lda + kc + seg * 8);
        }
        #pragma unroll
        for (int it = 0; it < WIT; it++) {          // W hi + lo
            int idx = tid + it * 256;
            int row = idx >> 2, seg = idx & 3;
            uint32_t off = (uint32_t)(row * SSTR + seg * 8) * 2;
            size_t go = (size_t)(n0 + row) * ldw + kc + seg * 8;
            CPA16(sb + A_BYTES + off, Wh + go);
            CPA16(sb + A_BYTES + W_BYTES + off, Wl + go);
        }
    };

    issue(0); CPCOMMIT();
    if (NC > 1) { issue(1); CPCOMMIT(); }

    for (int c = 0; c < NC; c++) {
        if (c + 2 < NC)      { issue(c + 2); CPCOMMIT(); CPWAIT2(); }
        else if (c + 1 < NC) { CPWAIT1(); }
        else                 { CPWAIT0(); }
        __syncthreads();

        const uint32_t sb  = smb + (uint32_t)(c % 3) * STAGEB;
        const uint32_t bA  = sb;
        const uint32_t bWh = sb + A_BYTES;
        const uint32_t bWl = sb + A_BYTES + W_BYTES;

        #pragma unroll
        for (int kk = 0; kk < 32; kk += 16) {
            const int col = kk + ((lane >> 4) << 3);
            uint32_t a0[4], a1[4];
            {
                int row = wm * 32 + (lane & 15);
                ldm4(a0, bA + (uint32_t)(row * SSTR + col) * 2u);
                ldm4(a1, bA + (uint32_t)((row + 16) * SSTR + col) * 2u);
            }
            #pragma unroll
            for (int t = 0; t < N16T; t++) {
                uint32_t bh[4], bl[4];
                int row = wn * WN + t * 16 + (lane & 15);
                uint32_t off = (uint32_t)(row * SSTR + col) * 2u;
                ldm4(bh, bWh + off);
                ldm4(bl, bWl + off);
                #pragma unroll
                for (int hs = 0; hs < 2; hs++) {
                    int nt = 2 * t + hs;
                    mma16816(acc[0][nt], a0, bh[hs], bh[2 + hs]);
                    mma16816(acc[1][nt], a1, bh[hs], bh[2 + hs]);
                    mma16816(acc[0][nt], a0, bl[hs], bl[2 + hs]);
                    mma16816(acc[1][nt], a1, bl[hs], bl[2 + hs]);
                }
            }
        }
        __syncthreads();
    }

    // epilogue
    #pragma unroll
    for (int mt = 0; mt < 2; mt++) {
        int r0 = m0 + wm * 32 + mt * 16 + (lane >> 2);
        int r1 = r0 + 8;
        int ib0 = 0, ib1 = 0;
        if (EPI == 1) { ib0 = idxp[r0]; ib1 = idxp[r1]; }
        #pragma unroll
        for (int nt = 0; nt < NT8; nt++) {
            int cc = n0 + wn * WN + nt * 8 + ((lane & 3) << 1);
            if (cc < N) {
                float bb0 = 0.f, bb1 = 0.f;
                if (EPI != 1 && bias) {
                    if (cc < nsplit) { bb0 = bias[cc]; bb1 = bias[cc + 1]; }
                    else             { bb0 = bias2[cc - nsplit]; bb1 = bias2[cc + 1 - nsplit]; }
                }
                #pragma unroll
                for (int p = 0; p < 2; p++) {
                    int r  = p ? r1 : r0;
                    int ib = p ? ib1 : ib0;
                    float x = acc[mt][nt][2 * p];
                    float y = acc[mt][nt][2 * p + 1];
                    if (EPI == 1) {
                        x += aux0[(size_t)ib * 1024 + cc];
                        y += aux0[(size_t)ib * 1024 + cc + 1];
                    } else {
                        x += bb0; y += bb1;
                    }
                    if (ACT) { x = fmaxf(x, 0.f); y = fmaxf(y, 0.f); }
                    if (EPI == 2) {
                        x = tanhf(aux0[(size_t)r * 256 + cc] + x)     * aux1[(size_t)r * 512 + 256 + cc];
                        y = tanhf(aux0[(size_t)r * 256 + cc + 1] + y) * aux1[(size_t)r * 512 + 256 + cc + 1];
                    }
                    size_t o = (size_t)r * ldc + cc;
                    if (OUTM & 1)
                        *reinterpret_cast<float2*>(&C[o]) = make_float2(x, y);
                    if (OUTM & 2)
                        *reinterpret_cast<uint32_t*>(Ch + o) = pack2h(__float2half(x), __float2half(y));
                }
            }
        }
    }
}

// ---------------------------------------------------------------------------
// Final heads: pv2 [B,96] = pol2(0:64) | val2(64:96)
// ---------------------------------------------------------------------------
__global__ void k_heads(const float* __restrict__ pv2,
                        const float* __restrict__ w_p, const float* __restrict__ b_p,
                        const float* __restrict__ w_v, const float* __restrict__ b_v,
                        float* __restrict__ out_val, float* __restrict__ out_pol) {
    __shared__ float sp[64][97];
    int r0 = blockIdx.x * 64;
    for (int i = threadIdx.x; i < 64 * 96; i += blockDim.x) {
        int r = i / 96, c = i - r * 96;
        sp[r][c] = pv2[(size_t)(r0 + r) * 96 + c];
    }
    __syncthreads();
    int t = threadIdx.x;
    if (t < 64) {
        int b = r0 + t;
        float p0 = b_p[0], p1 = b_p[1], p2 = b_p[2];
        #pragma unroll
        for (int k = 0; k < 64; k++) {
            float x = sp[t][k];
            p0 = fmaf(x, w_p[k], p0);
            p1 = fmaf(x, w_p[64 + k], p1);
            p2 = fmaf(x, w_p[128 + k], p2);
        }
        out_pol[(size_t)b * 3 + 0] = p0;
        out_pol[(size_t)b * 3 + 1] = p1;
        out_pol[(size_t)b * 3 + 2] = p2;
        float v = b_v[0];
        #pragma unroll
        for (int k = 0; k < 32; k++) v = fmaf(sp[t][64 + k], w_v[k], v);
        out_val[b] = v;
    }
}

// ---------------------------------------------------------------------------
// host launcher
// ---------------------------------------------------------------------------
extern "C" void kernel_launch(void* const* d_in, const int* in_sizes, int n_in,
                              void* d_out, int out_size) {
    const float* img   = (const float*)d_in[0];
    const int*   idx   = (const int*)  d_in[1];
    const float* hx_in = (const float*)d_in[2];
    const float* cx_in = (const float*)d_in[3];
    const float* query = (const float*)d_in[4];
    const float* emb   = (const float*)d_in[5];
    const float* w_ta  = (const float*)d_in[6];
    const float* b_ta  = (const float*)d_in[7];
    const float* w_ih  = (const float*)d_in[8];
    const float* w_hh  = (const float*)d_in[9];
    const float* b_ih  = (const float*)d_in[10];
    const float* b_hh  = (const float*)d_in[11];
    const float* w_q   = (const float*)d_in[12];
    const float* b_q   = (const float*)d_in[13];
    const float* w_k   = (const float*)d_in[14];
    const float* b_k   = (const float*)d_in[15];
    const float* w_ba  = (const float*)d_in[16];
    const float* b_ba  = (const float*)d_in[17];
    const float* w_at  = (const float*)d_in[18];
    const float* b_at  = (const float*)d_in[19];
    const float* w_p1  = (const float*)d_in[20];
    const float* b_p1  = (const float*)d_in[21];
    const float* w_p2  = (const float*)d_in[22];
    const float* b_p2  = (const float*)d_in[23];
    const float* w_p   = (const float*)d_in[24];
    const float* b_p   = (const float*)d_in[25];
    const float* w_v1  = (const float*)d_in[26];
    const float* b_v1  = (const float*)d_in[27];
    const float* w_v2  = (const float*)d_in[28];
    const float* b_v2  = (const float*)d_in[29];
    const float* w_v   = (const float*)d_in[30];
    const float* b_v   = (const float*)d_in[31];

    const int B = in_sizes[0] / 256;  // 32768

    float* F = nullptr;
    cudaGetSymbolAddress((void**)&F, g_f32);
    __half* HF = nullptr;
    cudaGetSymbolAddress((void**)&HF, g_hf);

    float* tab   = F + F_TAB;
    float* pre2  = F + F_PRE2;
    float* gates = F + F_GATES;
    float* mlpf  = F + F_MLP;
    float* qout  = F + F_QOUT;
    float* pv2   = F + F_PV2;

    float* out   = (float*)d_out;
    float* o_val = out;
    float* o_pol = out + (size_t)B;
    float* o_hx  = out + (size_t)B * 4;
    float* o_cx  = o_hx + (size_t)B * 256;

    // smem: 3 stages; stage = 10240 + 2*BN*80
    const int SM128 = 3 * (10240 + 2 * 128 * 80);  // 92160
    const int SM64  = 3 * (10240 + 2 * 64 * 80);   // 61440
    cudaFuncSetAttribute(mma_gemm<128, 0, 1, 1>, cudaFuncAttributeMaxDynamicSharedMemorySize, SM128);
    cudaFuncSetAttribute(mma_gemm<128, 1, 0, 1>, cudaFuncAttributeMaxDynamicSharedMemorySize, SM128);
    cudaFuncSetAttribute(mma_gemm<128, 1, 0, 3>, cudaFuncAttributeMaxDynamicSharedMemorySize, SM128);
    cudaFuncSetAttribute(mma_gemm<128, 1, 2, 2>, cudaFuncAttributeMaxDynamicSharedMemorySize, SM128);
    cudaFuncSetAttribute(mma_gemm<128, 1, 0, 2>, cudaFuncAttributeMaxDynamicSharedMemorySize, SM128);
    cudaFuncSetAttribute(mma_gemm<64, 1, 0, 2>,  cudaFuncAttributeMaxDynamicSharedMemorySize, SM64);
    cudaFuncSetAttribute(mma_gemm<64, 1, 0, 1>,  cudaFuncAttributeMaxDynamicSharedMemorySize, SM64);

    // K0: tables
    k0_tables<<<1, 1024>>>(emb, w_ta, b_ta, w_ih, b_ih, b_hh, tab, pre2);

    // fused weight split (9 segments, one launch)
    {
        WAll d;
        auto seg = [&](int i, const float* src, int srcld, int cols, int rows, int padrows,
                       size_t hoff, size_t loff) {
            d.s[i] = WSeg{src, nullptr, srcld, cols, rows, padrows * cols, 0,
                          (long long)hoff, (long long)loff};
        };
        seg(0, w_ih, 512, 256, 1024, 1024, H_WIH_H, H_WIH_L);
        seg(1, w_hh, 256, 256, 1024, 1024, H_WHH_H, H_WHH_L);
        seg(2, w_ba, 512, 512, 512, 512, H_WBA_H, H_WBA_L);
        seg(3, w_q,  256, 256, 256, 256, H_WQ_H,  H_WQ_L);
        seg(4, w_k,  256, 256, 256, 256, H_WK_H,  H_WK_L);
        seg(5, w_at, 512, 512, 256, 256, H_WAT_H, H_WAT_L);
        seg(6, w_p1, 256, 256, 128, 128, H_WPV_H, H_WPV_L);
        // w_v1 rows appended at row 128 of the 192x256 combined weight
        seg(7, w_v1, 256, 256, 64, 64, H_WPV_H + 128 * 256, H_WPV_L + 128 * 256);
        // block-diag [wp2|0 ; 0|wv2], 128x192 (rows 96:128 zero)
        d.s[8] = WSeg{w_p2, w_v2, 0, 0, 0, 128 * 192, 2, (long long)H_WC_H, (long long)H_WC_L};
        int total = 0;
        for (int i = 0; i < 9; i++) total += d.s[i].total;
        k_wsplit_all<<<(total + 255) / 256, 256>>>(d, HF);
    }

    // fused prep
    k_prep<<<(3 * B * 64 + 255) / 256, 256>>>(
        (const float4*)img, idx, tab, (const float4*)hx_in, (const float4*)query,
        HF + H_FUS, HF + H_HXI, HF + H_QRY, B * 64);

    // K2: gates = fus @ w_ih[:,:256]^T + hx @ w_hh^T + pre2[idx]
    mma_gemm<128, 0, 1, 1><<<dim3(8, B / 128), 256, SM128>>>(
        1024,
        HF + H_FUS, 256, HF + H_WIH_H, HF + H_WIH_L, 256, 256,
        HF + H_HXI, 256, HF + H_WHH_H, HF + H_WHH_L, 256, 256,
        nullptr, nullptr, 1 << 30, pre2, nullptr, idx, gates, nullptr, 1024);

    // K3: LSTM
    k_lstm<<<(B * 64 + 255) / 256, 256>>>(gates, cx_in, o_hx, o_cx, HF + H_HXO, B * 64);

    // K5: qout = relu(query @ w_q^T + b_q)  (fp32)
    mma_gemm<128, 1, 0, 1><<<dim3(2, B / 128), 256, SM128>>>(
        256,
        HF + H_QRY, 256, HF + H_WQ_H, HF + H_WQ_L, 256, 256,
        nullptr, 0, nullptr, nullptr, 0, 0,
        b_q, nullptr, 1 << 30, nullptr, nullptr, nullptr, qout, nullptr, 256);

    // K4: mlp = relu([fus|hx] @ w_ba^T + b_ba)  (fp32 + fp16)
    mma_gemm<128, 1, 0, 3><<<dim3(4, B / 128), 256, SM128>>>(
        512,
        HF + H_FUS, 256, HF + H_WBA_H, HF + H_WBA_L, 512, 256,
        HF + H_HXO, 256, HF + H_WBA_H + 256, HF + H_WBA_L + 256, 512, 256,
        b_ba, nullptr, 1 << 30, nullptr, nullptr, nullptr, mlpf, HF + H_MLP, 512);

    // K6: avec = tanh(qout + relu(key @ w_k^T + b_k)) * val  (fp16)
    mma_gemm<128, 1, 2, 2><<<dim3(2, B / 128), 256, SM128>>>(
        256,
        HF + H_MLP, 512, HF + H_WK_H, HF + H_WK_L, 256, 256,
        nullptr, 0, nullptr, nullptr, 0, 0,
        b_k, nullptr, 1 << 30, qout, mlpf, nullptr, nullptr, HF + H_AVEC, 256);

    // K7: attnw = relu([avec|hx] @ w_at^T + b_at)  (fp16)
    mma_gemm<128, 1, 0, 2><<<dim3(2, B / 128), 256, SM128>>>(
        256,
        HF + H_AVEC, 256, HF + H_WAT_H, HF + H_WAT_L, 512, 256,
        HF + H_HXO, 256, HF + H_WAT_H + 256, HF + H_WAT_L + 256, 512, 256,
        b_at, nullptr, 1 << 30, nullptr, nullptr, nullptr, nullptr, HF + H_ATT, 256);

    // K8: [pol1|val1] = relu(attnw @ [w_p1;w_v1]^T + [b_p1;b_v1])  N=192 (fp16)
    mma_gemm<64, 1, 0, 2><<<dim3(3, B / 128), 256, SM64>>>(
        192,
        HF + H_ATT, 256, HF + H_WPV_H, HF + H_WPV_L, 256, 256,
        nullptr, 0, nullptr, nullptr, 0, 0,
        b_p1, b_v1, 128, nullptr, nullptr, nullptr, nullptr, HF + H_P1V1, 192);

    // K9: [pol2|val2] = relu([pol1|val1] @ blockdiag(w_p2,w_v2)^T + [b_p2;b_v2])  N=96 (fp32)
    mma_gemm<64, 1, 0, 1><<<dim3(2, B / 128), 256, SM64>>>(
        96,
        HF + H_P1V1, 192, HF + H_WC_H, HF + H_WC_L, 192, 192,
        nullptr, 0, nullptr, nullptr, 0, 0,
        b_p2, b_v2, 64, nullptr, nullptr, nullptr, pv2, nullptr, 96);

    // K10: heads
    k_heads<<<B / 64, 256>>>(pv2, w_p, b_p, w_v, b_v, o_val, o_pol);
}

// round 9
// speedup vs baseline: 1.5643x; 1.1709x over previous
#include <cuda_runtime.h>
#include <cuda_fp16.h>
#include <cstdint>
#include <math.h>

// ---------------------------------------------------------------------------
// Actor_Critic — single-pass fp16 MMA pipeline (weights + activations fp16,
// fp32 accumulate). 256-thread GEMM CTAs, 3-stage cp.async, 2 CTAs/SM.
// (tcgen05 is unavailable: harness PTX target is compute_103 family-generic.)
// ---------------------------------------------------------------------------

constexpr size_t S_B = 32768;

// fp32 scratch
constexpr size_t F_TAB   = 0;
constexpr size_t F_PRE2  = 1024;
constexpr size_t F_GATES = 8192;
constexpr size_t F_MLP   = F_GATES + S_B * 1024;
constexpr size_t F_QOUT  = F_MLP   + S_B * 512;
constexpr size_t F_PV2   = F_QOUT  + S_B * 256;      // [B,96]: pol2 0:64 | val2 64:96
constexpr size_t F_END   = F_PV2   + S_B * 96;
__device__ float g_f32[F_END];

// fp16 scratch
constexpr size_t H_WIH   = 0;                        // 1024x256
constexpr size_t H_WHH   = H_WIH   + 262144;         // 1024x256
constexpr size_t H_WBA   = H_WHH   + 262144;         // 512x512
constexpr size_t H_WQ    = H_WBA   + 262144;         // 256x256
constexpr size_t H_WK    = H_WQ    + 65536;          // 256x256
constexpr size_t H_WAT   = H_WK    + 65536;          // 256x512
constexpr size_t H_WPV   = H_WAT   + 131072;         // 192x256
constexpr size_t H_WC    = H_WPV   + 49152;          // 128x192 block-diag
constexpr size_t H_FUS   = H_WC    + 24576;          // B*256
constexpr size_t H_HXI   = H_FUS   + S_B * 256;
constexpr size_t H_QRY   = H_HXI   + S_B * 256;
constexpr size_t H_HXO   = H_QRY   + S_B * 256;
constexpr size_t H_MLP   = H_HXO   + S_B * 256;      // B*512
constexpr size_t H_AVEC  = H_MLP   + S_B * 512;
constexpr size_t H_ATT   = H_AVEC  + S_B * 256;
constexpr size_t H_P1V1  = H_ATT   + S_B * 256;      // B*192
constexpr size_t H_END   = H_P1V1  + S_B * 192;
__device__ __half g_hf[H_END];

__device__ __forceinline__ float sigmoidf_(float x) { return 1.f / (1.f + expf(-x)); }
__device__ __forceinline__ uint32_t pack2h(__half a, __half b) {
    return (uint32_t)__half_as_ushort(a) | ((uint32_t)__half_as_ushort(b) << 16);
}

// ---------------------------------------------------------------------------
// K0: gated_att table (4x256) + pre2 table (4x1024)
// ---------------------------------------------------------------------------
__global__ void k0_tables(const float* __restrict__ emb,  const float* __restrict__ w_ta,
                          const float* __restrict__ b_ta, const float* __restrict__ w_ih,
                          const float* __restrict__ b_ih, const float* __restrict__ b_hh,
                          float* __restrict__ tab, float* __restrict__ pre2) {
    int t = threadIdx.x;  // 1024
    {
        int r = t >> 8, j = t & 255;
        float s = b_ta[j];
        #pragma unroll
        for (int k = 0; k < 25; k++) s += emb[r * 25 + k] * w_ta[j * 25 + k];
        tab[t] = sigmoidf_(s);
    }
    __syncthreads();
    {
        int j = t;
        const float* wrow = &w_ih[(size_t)j * 512 + 256];
        float base = b_ih[j] + b_hh[j];
        for (int r = 0; r < 4; r++) {
            const float* tr = &tab[r * 256];
            float s = base;
            for (int k = 0; k < 256; k++) s += tr[k] * wrow[k];
            pre2[r * 1024 + j] = s;
        }
    }
}

// ---------------------------------------------------------------------------
// fused weight convert to fp16. mode 0: normal; mode 2: p2/v2 block-diag.
// ---------------------------------------------------------------------------
struct WSeg { const float* src; const float* src2; int srcld, cols, rows, total, mode;
              long long hoff; };
struct WAll { WSeg s[9]; };

__global__ void k_wsplit_all(WAll d, __half* __restrict__ base) {
    int i = blockIdx.x * blockDim.x + threadIdx.x;
    #pragma unroll
    for (int s = 0; s < 9; s++) {
        const WSeg& g = d.s[s];
        if (i < g.total) {
            float v;
            if (g.mode == 0) {
                int r = i / g.cols, c = i - r * g.cols;
                v = (r < g.rows) ? g.src[(size_t)r * g.srcld + c] : 0.f;
            } else {
                int r = i / 192, c = i - r * 192;
                if (r < 64)       v = (c < 128) ? g.src[r * 128 + c] : 0.f;
                else if (c >= 128 && r - 64 < 32) v = g.src2[(r - 64) * 64 + (c - 128)];
                else              v = 0.f;
            }
            base[g.hoff + i] = __float2half(v);
            return;
        }
        i -= g.total;
    }
}

// ---------------------------------------------------------------------------
// fused prep: region 0 fusion(img*tab[idx]); 1: round hx_in; 2: round query
// ---------------------------------------------------------------------------
__global__ void k_prep(const float4* __restrict__ img, const int* __restrict__ idx,
                       const float* __restrict__ tab,
                       const float4* __restrict__ hx_in, const float4* __restrict__ query,
                       __half* __restrict__ fus, __half* __restrict__ hxi,
                       __half* __restrict__ qry, int nq) {
    int i = blockIdx.x * blockDim.x + threadIdx.x;
    int reg = 0;
    if (i >= nq) { i -= nq; reg = 1; }
    if (i >= nq) { i -= nq; reg = 2; }
    if (i >= nq) return;
    float4 v;
    __half* dst;
    if (reg == 0) {
        int b = i >> 6, j4 = (i & 63) << 2;
        float4 g = *reinterpret_cast<const float4*>(tab + idx[b] * 256 + j4);
        v = img[i];
        v.x *= g.x; v.y *= g.y; v.z *= g.z; v.w *= g.w;
        dst = fus;
    } else if (reg == 1) { v = hx_in[i]; dst = hxi; }
    else                 { v = query[i]; dst = qry; }
    uint2 u = make_uint2(pack2h(__float2half(v.x), __float2half(v.y)),
                         pack2h(__float2half(v.z), __float2half(v.w)));
    *reinterpret_cast<uint2*>(dst + (size_t)i * 4) = u;
}

// ---------------------------------------------------------------------------
// K3: LSTM -> hx,cx fp32 (outputs) + hx fp16
// ---------------------------------------------------------------------------
__global__ void k_lstm(const float* __restrict__ gates, const float* __restrict__ cx_in,
                       float* __restrict__ hx_out, float* __restrict__ cx_out,
                       __half* __restrict__ hxo, int totalq) {
    int i = blockIdx.x * blockDim.x + threadIdx.x;
    if (i >= totalq) return;
    int b = i >> 6, j = (i & 63) << 2;
    const float* g = gates + (size_t)b * 1024 + j;
    float4 gi = *reinterpret_cast<const float4*>(g);
    float4 gf = *reinterpret_cast<const float4*>(g + 256);
    float4 gg = *reinterpret_cast<const float4*>(g + 512);
    float4 go = *reinterpret_cast<const float4*>(g + 768);
    float4 c0 = *reinterpret_cast<const float4*>(cx_in + (size_t)b * 256 + j);
    float4 ho, co;
    co.x = sigmoidf_(gf.x) * c0.x + sigmoidf_(gi.x) * tanhf(gg.x); ho.x = sigmoidf_(go.x) * tanhf(co.x);
    co.y = sigmoidf_(gf.y) * c0.y + sigmoidf_(gi.y) * tanhf(gg.y); ho.y = sigmoidf_(go.y) * tanhf(co.y);
    co.z = sigmoidf_(gf.z) * c0.z + sigmoidf_(gi.z) * tanhf(gg.z); ho.z = sigmoidf_(go.z) * tanhf(co.z);
    co.w = sigmoidf_(gf.w) * c0.w + sigmoidf_(gi.w) * tanhf(gg.w); ho.w = sigmoidf_(go.w) * tanhf(co.w);
    size_t o = (size_t)b * 256 + j;
    *reinterpret_cast<float4*>(hx_out + o) = ho;
    *reinterpret_cast<float4*>(cx_out + o) = co;
    uint2 u = make_uint2(pack2h(__float2half(ho.x), __float2half(ho.y)),
                         pack2h(__float2half(ho.z), __float2half(ho.w)));
    *reinterpret_cast<uint2*>(hxo + o) = u;
}

// ---------------------------------------------------------------------------
// MMA / cp.async helpers
// ---------------------------------------------------------------------------
__device__ __forceinline__ void ldm4(uint32_t* r, uint32_t addr) {
    asm volatile("ldmatrix.sync.aligned.m8n8.x4.shared.b16 {%0,%1,%2,%3}, [%4];"
                 : "=r"(r[0]), "=r"(r[1]), "=r"(r[2]), "=r"(r[3]) : "r"(addr));
}
__device__ __forceinline__ void mma16816(float* c, const uint32_t* a, uint32_t b0, uint32_t b1) {
    asm volatile(
        "mma.sync.aligned.m16n8k16.row.col.f32.f16.f16.f32 "
        "{%0,%1,%2,%3}, {%4,%5,%6,%7}, {%8,%9}, {%0,%1,%2,%3};"
        : "+f"(c[0]), "+f"(c[1]), "+f"(c[2]), "+f"(c[3])
        : "r"(a[0]), "r"(a[1]), "r"(a[2]), "r"(a[3]), "r"(b0), "r"(b1));
}
#define CPA16(dst, src) asm volatile("cp.async.cg.shared.global [%0], [%1], 16;\n" :: "r"(dst), "l"(src))
#define CPCOMMIT()      asm volatile("cp.async.commit_group;\n")
#define CPWAIT2()       asm volatile("cp.async.wait_group 2;\n")
#define CPWAIT1()       asm volatile("cp.async.wait_group 1;\n")
#define CPWAIT0()       asm volatile("cp.async.wait_group 0;\n")

// ---------------------------------------------------------------------------
// GEMM: C = epi( sum_seg A_seg @ W_seg^T ), all fp16 single pass, fp32 acc.
// 256 threads, 8 warps (4m x 2n), BM=128, 3-stage cp.async, 2 CTAs/SM.
// EPI 0: +bias (split at nsplit into bias/bias2), relu if ACT
// EPI 1: +aux0[idxp[m]*1024+n]
// EPI 2: (+bias, relu) -> tanh(aux0[m*256+n]+v) * aux1[m*512+256+n]
// OUTM bit0: fp32 C; bit1: fp16 Ch.
// ---------------------------------------------------------------------------
template <int BN, int ACT, int EPI, int OUTM>
__global__ void __launch_bounds__(256, 2)
mma_gemm(int N,
         const __half* __restrict__ A0, int lda0,
         const __half* __restrict__ W0, int ldw0, int K0,
         const __half* __restrict__ A1, int lda1,
         const __half* __restrict__ W1, int ldw1, int K1,
         const float* __restrict__ bias, const float* __restrict__ bias2, int nsplit,
         const float* __restrict__ aux0, const float* __restrict__ aux1,
         const int* __restrict__ idxp,
         float* __restrict__ C, __half* __restrict__ Ch, int ldc) {
    constexpr int WN      = BN / 2;                 // warp n-extent (2 warps in n)
    constexpr int NT8     = WN / 8;
    constexpr int N16T    = WN / 16;
    constexpr int SSTR    = 40;                     // halves per smem row (80B, conflict-free)
    constexpr int A_BYTES = 128 * SSTR * 2;         // 10240
    constexpr int W_BYTES = BN * SSTR * 2;
    constexpr int STAGEB  = A_BYTES + W_BYTES;
    constexpr int WIT     = BN / 64;                // W cp.async iters (slots = BN*4)

    extern __shared__ __half smem_dyn[];

    const int tid  = threadIdx.x;
    const int lane = tid & 31;
    const int wid  = tid >> 5;
    const int wm = wid & 3, wn = wid >> 2;          // 4 x 2 warps
    const int m0 = blockIdx.y * 128;
    const int n0 = blockIdx.x * BN;

    const uint32_t smb = (uint32_t)__cvta_generic_to_shared(smem_dyn);

    float acc[2][NT8][4];
    #pragma unroll
    for (int i = 0; i < 2; i++)
        #pragma unroll
        for (int j = 0; j < NT8; j++)
            #pragma unroll
            for (int q = 0; q < 4; q++) acc[i][j][q] = 0.f;

    const int nc0 = K0 >> 5;
    const int NC  = nc0 + (K1 >> 5);

    auto issue = [&](int c) {
        const __half *A, *W;
        int lda, ldw, kc;
        if (c < nc0) { A = A0; W = W0; lda = lda0; ldw = ldw0; kc = c << 5; }
        else         { A = A1; W = W1; lda = lda1; ldw = ldw1; kc = (c - nc0) << 5; }
        const uint32_t sb = smb + (uint32_t)(c % 3) * STAGEB;
        #pragma unroll
        for (int it = 0; it < 2; it++) {            // A: 128 rows x 4 segs
            int idx = tid + it * 256;
            int row = idx >> 2, seg = idx & 3;
            uint32_t off = (uint32_t)(row * SSTR + seg * 8) * 2;
            CPA16(sb + off, A + (size_t)(m0 + row) * lda + kc + seg * 8);
        }
        #pragma unroll
        for (int it = 0; it < WIT; it++) {          // W
            int idx = tid + it * 256;
            int row = idx >> 2, seg = idx & 3;
            uint32_t off = (uint32_t)(row * SSTR + seg * 8) * 2;
            CPA16(sb + A_BYTES + off, W + (size_t)(n0 + row) * ldw + kc + seg * 8);
        }
    };

    issue(0); CPCOMMIT();
    if (NC > 1) { issue(1); CPCOMMIT(); }

    for (int c = 0; c < NC; c++) {
        if (c + 2 < NC)      { issue(c + 2); CPCOMMIT(); CPWAIT2(); }
        else if (c + 1 < NC) { CPWAIT1(); }
        else                 { CPWAIT0(); }
        __syncthreads();

        const uint32_t sb = smb + (uint32_t)(c % 3) * STAGEB;
        const uint32_t bA = sb;
        const uint32_t bW = sb + A_BYTES;

        #pragma unroll
        for (int kk = 0; kk < 32; kk += 16) {
            const int col = kk + ((lane >> 4) << 3);
            uint32_t a0[4], a1[4];
            {
                int row = wm * 32 + (lane & 15);
                ldm4(a0, bA + (uint32_t)(row * SSTR + col) * 2u);
                ldm4(a1, bA + (uint32_t)((row + 16) * SSTR + col) * 2u);
            }
            #pragma unroll
            for (int t = 0; t < N16T; t++) {
                uint32_t bh[4];
                int row = wn * WN + t * 16 + (lane & 15);
                ldm4(bh, bW + (uint32_t)(row * SSTR + col) * 2u);
                #pragma unroll
                for (int hs = 0; hs < 2; hs++) {
                    int nt = 2 * t + hs;
                    mma16816(acc[0][nt], a0, bh[hs], bh[2 + hs]);
                    mma16816(acc[1][nt], a1, bh[hs], bh[2 + hs]);
                }
            }
        }
        __syncthreads();
    }

    // epilogue
    #pragma unroll
    for (int mt = 0; mt < 2; mt++) {
        int r0 = m0 + wm * 32 + mt * 16 + (lane >> 2);
        int r1 = r0 + 8;
        int ib0 = 0, ib1 = 0;
        if (EPI == 1) { ib0 = idxp[r0]; ib1 = idxp[r1]; }
        #pragma unroll
        for (int nt = 0; nt < NT8; nt++) {
            int cc = n0 + wn * WN + nt * 8 + ((lane & 3) << 1);
            if (cc < N) {
                float bb0 = 0.f, bb1 = 0.f;
                if (EPI != 1 && bias) {
                    if (cc < nsplit) { bb0 = bias[cc]; bb1 = bias[cc + 1]; }
                    else             { bb0 = bias2[cc - nsplit]; bb1 = bias2[cc + 1 - nsplit]; }
                }
                #pragma unroll
                for (int p = 0; p < 2; p++) {
                    int r  = p ? r1 : r0;
                    int ib = p ? ib1 : ib0;
                    float x = acc[mt][nt][2 * p];
                    float y = acc[mt][nt][2 * p + 1];
                    if (EPI == 1) {
                        x += aux0[(size_t)ib * 1024 + cc];
                        y += aux0[(size_t)ib * 1024 + cc + 1];
                    } else {
                        x += bb0; y += bb1;
                    }
                    if (ACT) { x = fmaxf(x, 0.f); y = fmaxf(y, 0.f); }
                    if (EPI == 2) {
                        x = tanhf(aux0[(size_t)r * 256 + cc] + x)     * aux1[(size_t)r * 512 + 256 + cc];
                        y = tanhf(aux0[(size_t)r * 256 + cc + 1] + y) * aux1[(size_t)r * 512 + 256 + cc + 1];
                    }
                    size_t o = (size_t)r * ldc + cc;
                    if (OUTM & 1)
                        *reinterpret_cast<float2*>(&C[o]) = make_float2(x, y);
                    if (OUTM & 2)
                        *reinterpret_cast<uint32_t*>(Ch + o) = pack2h(__float2half(x), __float2half(y));
                }
            }
        }
    }
}

// ---------------------------------------------------------------------------
// Final heads: pv2 [B,96] = pol2(0:64) | val2(64:96)
// ---------------------------------------------------------------------------
__global__ void k_heads(const float* __restrict__ pv2,
                        const float* __restrict__ w_p, const float* __restrict__ b_p,
                        const float* __restrict__ w_v, const float* __restrict__ b_v,
                        float* __restrict__ out_val, float* __restrict__ out_pol) {
    __shared__ float sp[64][97];
    int r0 = blockIdx.x * 64;
    for (int i = threadIdx.x; i < 64 * 96; i += blockDim.x) {
        int r = i / 96, c = i - r * 96;
        sp[r][c] = pv2[(size_t)(r0 + r) * 96 + c];
    }
    __syncthreads();
    int t = threadIdx.x;
    if (t < 64) {
        int b = r0 + t;
        float p0 = b_p[0], p1 = b_p[1], p2 = b_p[2];
        #pragma unroll
        for (int k = 0; k < 64; k++) {
            float x = sp[t][k];
            p0 = fmaf(x, w_p[k], p0);
            p1 = fmaf(x, w_p[64 + k], p1);
            p2 = fmaf(x, w_p[128 + k], p2);
        }
        out_pol[(size_t)b * 3 + 0] = p0;
        out_pol[(size_t)b * 3 + 1] = p1;
        out_pol[(size_t)b * 3 + 2] = p2;
        float v = b_v[0];
        #pragma unroll
        for (int k = 0; k < 32; k++) v = fmaf(sp[t][64 + k], w_v[k], v);
        out_val[b] = v;
    }
}

// ---------------------------------------------------------------------------
// host launcher
// ---------------------------------------------------------------------------
extern "C" void kernel_launch(void* const* d_in, const int* in_sizes, int n_in,
                              void* d_out, int out_size) {
    const float* img   = (const float*)d_in[0];
    const int*   idx   = (const int*)  d_in[1];
    const float* hx_in = (const float*)d_in[2];
    const float* cx_in = (const float*)d_in[3];
    const float* query = (const float*)d_in[4];
    const float* emb   = (const float*)d_in[5];
    const float* w_ta  = (const float*)d_in[6];
    const float* b_ta  = (const float*)d_in[7];
    const float* w_ih  = (const float*)d_in[8];
    const float* w_hh  = (const float*)d_in[9];
    const float* b_ih  = (const float*)d_in[10];
    const float* b_hh  = (const float*)d_in[11];
    const float* w_q   = (const float*)d_in[12];
    const float* b_q   = (const float*)d_in[13];
    const float* w_k   = (const float*)d_in[14];
    const float* b_k   = (const float*)d_in[15];
    const float* w_ba  = (const float*)d_in[16];
    const float* b_ba  = (const float*)d_in[17];
    const float* w_at  = (const float*)d_in[18];
    const float* b_at  = (const float*)d_in[19];
    const float* w_p1  = (const float*)d_in[20];
    const float* b_p1  = (const float*)d_in[21];
    const float* w_p2  = (const float*)d_in[22];
    const float* b_p2  = (const float*)d_in[23];
    const float* w_p   = (const float*)d_in[24];
    const float* b_p   = (const float*)d_in[25];
    const float* w_v1  = (const float*)d_in[26];
    const float* b_v1  = (const float*)d_in[27];
    const float* w_v2  = (const float*)d_in[28];
    const float* b_v2  = (const float*)d_in[29];
    const float* w_v   = (const float*)d_in[30];
    const float* b_v   = (const float*)d_in[31];

    const int B = in_sizes[0] / 256;  // 32768

    float* F = nullptr;
    cudaGetSymbolAddress((void**)&F, g_f32);
    __half* HF = nullptr;
    cudaGetSymbolAddress((void**)&HF, g_hf);

    float* tab   = F + F_TAB;
    float* pre2  = F + F_PRE2;
    float* gates = F + F_GATES;
    float* mlpf  = F + F_MLP;
    float* qout  = F + F_QOUT;
    float* pv2   = F + F_PV2;

    float* out   = (float*)d_out;
    float* o_val = out;
    float* o_pol = out + (size_t)B;
    float* o_hx  = out + (size_t)B * 4;
    float* o_cx  = o_hx + (size_t)B * 256;

    // smem: 3 stages; stage = 10240 + BN*80
    const int SM128 = 3 * (10240 + 128 * 80);  // 61440
    const int SM64  = 3 * (10240 + 64 * 80);   // 46080
    cudaFuncSetAttribute(mma_gemm<128, 0, 1, 1>, cudaFuncAttributeMaxDynamicSharedMemorySize, SM128);
    cudaFuncSetAttribute(mma_gemm<128, 1, 0, 1>, cudaFuncAttributeMaxDynamicSharedMemorySize, SM128);
    cudaFuncSetAttribute(mma_gemm<128, 1, 0, 3>, cudaFuncAttributeMaxDynamicSharedMemorySize, SM128);
    cudaFuncSetAttribute(mma_gemm<128, 1, 2, 2>, cudaFuncAttributeMaxDynamicSharedMemorySize, SM128);
    cudaFuncSetAttribute(mma_gemm<128, 1, 0, 2>, cudaFuncAttributeMaxDynamicSharedMemorySize, SM128);
    cudaFuncSetAttribute(mma_gemm<64, 1, 0, 2>,  cudaFuncAttributeMaxDynamicSharedMemorySize, SM64);
    cudaFuncSetAttribute(mma_gemm<64, 1, 0, 1>,  cudaFuncAttributeMaxDynamicSharedMemorySize, SM64);

    // K0: tables
    k0_tables<<<1, 1024>>>(emb, w_ta, b_ta, w_ih, b_ih, b_hh, tab, pre2);

    // fused weight convert (9 segments, one launch)
    {
        WAll d;
        auto seg = [&](int i, const float* src, int srcld, int cols, int rows, int padrows,
                       size_t hoff) {
            d.s[i] = WSeg{src, nullptr, srcld, cols, rows, padrows * cols, 0, (long long)hoff};
        };
        seg(0, w_ih, 512, 256, 1024, 1024, H_WIH);
        seg(1, w_hh, 256, 256, 1024, 1024, H_WHH);
        seg(2, w_ba, 512, 512, 512, 512, H_WBA);
        seg(3, w_q,  256, 256, 256, 256, H_WQ);
        seg(4, w_k,  256, 256, 256, 256, H_WK);
        seg(5, w_at, 512, 512, 256, 256, H_WAT);
        seg(6, w_p1, 256, 256, 128, 128, H_WPV);
        seg(7, w_v1, 256, 256, 64, 64, H_WPV + 128 * 256);
        d.s[8] = WSeg{w_p2, w_v2, 0, 0, 0, 128 * 192, 2, (long long)H_WC};
        int total = 0;
        for (int i = 0; i < 9; i++) total += d.s[i].total;
        k_wsplit_all<<<(total + 255) / 256, 256>>>(d, HF);
    }

    // fused prep
    k_prep<<<(3 * B * 64 + 255) / 256, 256>>>(
        (const float4*)img, idx, tab, (const float4*)hx_in, (const float4*)query,
        HF + H_FUS, HF + H_HXI, HF + H_QRY, B * 64);

    // K2: gates = fus @ w_ih[:,:256]^T + hx @ w_hh^T + pre2[idx]
    mma_gemm<128, 0, 1, 1><<<dim3(8, B / 128), 256, SM128>>>(
        1024,
        HF + H_FUS, 256, HF + H_WIH, 256, 256,
        HF + H_HXI, 256, HF + H_WHH, 256, 256,
        nullptr, nullptr, 1 << 30, pre2, nullptr, idx, gates, nullptr, 1024);

    // K3: LSTM
    k_lstm<<<(B * 64 + 255) / 256, 256>>>(gates, cx_in, o_hx, o_cx, HF + H_HXO, B * 64);

    // K5: qout = relu(query @ w_q^T + b_q)  (fp32)
    mma_gemm<128, 1, 0, 1><<<dim3(2, B / 128), 256, SM128>>>(
        256,
        HF + H_QRY, 256, HF + H_WQ, 256, 256,
        nullptr, 0, nullptr, 0, 0,
        b_q, nullptr, 1 << 30, nullptr, nullptr, nullptr, qout, nullptr, 256);

    // K4: mlp = relu([fus|hx] @ w_ba^T + b_ba)  (fp32 + fp16)
    mma_gemm<128, 1, 0, 3><<<dim3(4, B / 128), 256, SM128>>>(
        512,
        HF + H_FUS, 256, HF + H_WBA, 512, 256,
        HF + H_HXO, 256, HF + H_WBA + 256, 512, 256,
        b_ba, nullptr, 1 << 30, nullptr, nullptr, nullptr, mlpf, HF + H_MLP, 512);

    // K6: avec = tanh(qout + relu(key @ w_k^T + b_k)) * val  (fp16)
    mma_gemm<128, 1, 2, 2><<<dim3(2, B / 128), 256, SM128>>>(
        256,
        HF + H_MLP, 512, HF + H_WK, 256, 256,
        nullptr, 0, nullptr, 0, 0,
        b_k, nullptr, 1 << 30, qout, mlpf, nullptr, nullptr, HF + H_AVEC, 256);

    // K7: attnw = relu([avec|hx] @ w_at^T + b_at)  (fp16)
    mma_gemm<128, 1, 0, 2><<<dim3(2, B / 128), 256, SM128>>>(
        256,
        HF + H_AVEC, 256, HF + H_WAT, 512, 256,
        HF + H_HXO, 256, HF + H_WAT + 256, 512, 256,
        b_at, nullptr, 1 << 30, nullptr, nullptr, nullptr, nullptr, HF + H_ATT, 256);

    // K8: [pol1|val1] = relu(attnw @ [w_p1;w_v1]^T + [b_p1;b_v1])  N=192 (fp16)
    mma_gemm<64, 1, 0, 2><<<dim3(3, B / 128), 256, SM64>>>(
        192,
        HF + H_ATT, 256, HF + H_WPV, 256, 256,
        nullptr, 0, nullptr, 0, 0,
        b_p1, b_v1, 128, nullptr, nullptr, nullptr, nullptr, HF + H_P1V1, 192);

    // K9: [pol2|val2] = relu([pol1|val1] @ blockdiag(w_p2,w_v2)^T + [b_p2;b_v2])  N=96 (fp32)
    mma_gemm<64, 1, 0, 1><<<dim3(2, B / 128), 256, SM64>>>(
        96,
        HF + H_P1V1, 192, HF + H_WC, 192, 192,
        nullptr, 0, nullptr, 0, 0,
        b_p2, b_v2, 64, nullptr, nullptr, nullptr, pv2, nullptr, 96);

    // K10: heads
    k_heads<<<B / 64, 256>>>(pv2, w_p, b_p, w_v, b_v, o_val, o_pol);
}

// round 10
// speedup vs baseline: 1.6113x; 1.0300x over previous
#include <cuda_runtime.h>
#include <cuda_fp16.h>
#include <cstdint>
#include <math.h>

// ---------------------------------------------------------------------------
// Actor_Critic — single-pass fp16 MMA pipeline (weights + activations fp16,
// fp32 accumulate). 256-thread GEMM CTAs, K64 chunks, 3-stage cp.async ring,
// ONE barrier per chunk, 2 CTAs/SM.
// ---------------------------------------------------------------------------

constexpr size_t S_B = 32768;

// fp32 scratch
constexpr size_t F_TAB   = 0;
constexpr size_t F_PRE2  = 1024;
constexpr size_t F_GATES = 8192;
constexpr size_t F_MLP   = F_GATES + S_B * 1024;
constexpr size_t F_QOUT  = F_MLP   + S_B * 512;
constexpr size_t F_PV2   = F_QOUT  + S_B * 256;      // [B,96]: pol2 0:64 | val2 64:96
constexpr size_t F_END   = F_PV2   + S_B * 96;
__device__ float g_f32[F_END];

// fp16 scratch
constexpr size_t H_WIH   = 0;                        // 1024x256
constexpr size_t H_WHH   = H_WIH   + 262144;         // 1024x256
constexpr size_t H_WBA   = H_WHH   + 262144;         // 512x512
constexpr size_t H_WQ    = H_WBA   + 262144;         // 256x256
constexpr size_t H_WK    = H_WQ    + 65536;          // 256x256
constexpr size_t H_WAT   = H_WK    + 65536;          // 256x512
constexpr size_t H_WPV   = H_WAT   + 131072;         // 192x256
constexpr size_t H_WC    = H_WPV   + 49152;          // 128x192 block-diag
constexpr size_t H_FUS   = H_WC    + 24576;          // B*256
constexpr size_t H_HXI   = H_FUS   + S_B * 256;
constexpr size_t H_QRY   = H_HXI   + S_B * 256;
constexpr size_t H_HXO   = H_QRY   + S_B * 256;
constexpr size_t H_MLP   = H_HXO   + S_B * 256;      // B*512
constexpr size_t H_AVEC  = H_MLP   + S_B * 512;
constexpr size_t H_ATT   = H_AVEC  + S_B * 256;
constexpr size_t H_P1V1  = H_ATT   + S_B * 256;      // B*192
constexpr size_t H_END   = H_P1V1  + S_B * 192;
__device__ __half g_hf[H_END];

__device__ __forceinline__ float sigmoidf_(float x) { return 1.f / (1.f + expf(-x)); }
__device__ __forceinline__ uint32_t pack2h(__half a, __half b) {
    return (uint32_t)__half_as_ushort(a) | ((uint32_t)__half_as_ushort(b) << 16);
}

// ---------------------------------------------------------------------------
// K0: gated_att table (4x256) + pre2 table (4x1024)
// ---------------------------------------------------------------------------
__global__ void k0_tables(const float* __restrict__ emb,  const float* __restrict__ w_ta,
                          const float* __restrict__ b_ta, const float* __restrict__ w_ih,
                          const float* __restrict__ b_ih, const float* __restrict__ b_hh,
                          float* __restrict__ tab, float* __restrict__ pre2) {
    int t = threadIdx.x;  // 1024
    {
        int r = t >> 8, j = t & 255;
        float s = b_ta[j];
        #pragma unroll
        for (int k = 0; k < 25; k++) s += emb[r * 25 + k] * w_ta[j * 25 + k];
        tab[t] = sigmoidf_(s);
    }
    __syncthreads();
    {
        int j = t;
        const float* wrow = &w_ih[(size_t)j * 512 + 256];
        float base = b_ih[j] + b_hh[j];
        for (int r = 0; r < 4; r++) {
            const float* tr = &tab[r * 256];
            float s = base;
            for (int k = 0; k < 256; k++) s += tr[k] * wrow[k];
            pre2[r * 1024 + j] = s;
        }
    }
}

// ---------------------------------------------------------------------------
// fused weight convert to fp16. mode 0: normal; mode 2: p2/v2 block-diag.
// ---------------------------------------------------------------------------
struct WSeg { const float* src; const float* src2; int srcld, cols, rows, total, mode;
              long long hoff; };
struct WAll { WSeg s[9]; };

__global__ void k_wsplit_all(WAll d, __half* __restrict__ base) {
    int i = blockIdx.x * blockDim.x + threadIdx.x;
    #pragma unroll
    for (int s = 0; s < 9; s++) {
        const WSeg& g = d.s[s];
        if (i < g.total) {
            float v;
            if (g.mode == 0) {
                int r = i / g.cols, c = i - r * g.cols;
                v = (r < g.rows) ? g.src[(size_t)r * g.srcld + c] : 0.f;
            } else {
                int r = i / 192, c = i - r * 192;
                if (r < 64)       v = (c < 128) ? g.src[r * 128 + c] : 0.f;
                else if (c >= 128 && r - 64 < 32) v = g.src2[(r - 64) * 64 + (c - 128)];
                else              v = 0.f;
            }
            base[g.hoff + i] = __float2half(v);
            return;
        }
        i -= g.total;
    }
}

// ---------------------------------------------------------------------------
// fused prep: region 0 fusion(img*tab[idx]); 1: round hx_in; 2: round query
// ---------------------------------------------------------------------------
__global__ void k_prep(const float4* __restrict__ img, const int* __restrict__ idx,
                       const float* __restrict__ tab,
                       const float4* __restrict__ hx_in, const float4* __restrict__ query,
                       __half* __restrict__ fus, __half* __restrict__ hxi,
                       __half* __restrict__ qry, int nq) {
    int i = blockIdx.x * blockDim.x + threadIdx.x;
    int reg = 0;
    if (i >= nq) { i -= nq; reg = 1; }
    if (i >= nq) { i -= nq; reg = 2; }
    if (i >= nq) return;
    float4 v;
    __half* dst;
    if (reg == 0) {
        int b = i >> 6, j4 = (i & 63) << 2;
        float4 g = *reinterpret_cast<const float4*>(tab + idx[b] * 256 + j4);
        v = img[i];
        v.x *= g.x; v.y *= g.y; v.z *= g.z; v.w *= g.w;
        dst = fus;
    } else if (reg == 1) { v = hx_in[i]; dst = hxi; }
    else                 { v = query[i]; dst = qry; }
    uint2 u = make_uint2(pack2h(__float2half(v.x), __float2half(v.y)),
                         pack2h(__float2half(v.z), __float2half(v.w)));
    *reinterpret_cast<uint2*>(dst + (size_t)i * 4) = u;
}

// ---------------------------------------------------------------------------
// K3: LSTM -> hx,cx fp32 (outputs) + hx fp16
// ---------------------------------------------------------------------------
__global__ void k_lstm(const float* __restrict__ gates, const float* __restrict__ cx_in,
                       float* __restrict__ hx_out, float* __restrict__ cx_out,
                       __half* __restrict__ hxo, int totalq) {
    int i = blockIdx.x * blockDim.x + threadIdx.x;
    if (i >= totalq) return;
    int b = i >> 6, j = (i & 63) << 2;
    const float* g = gates + (size_t)b * 1024 + j;
    float4 gi = *reinterpret_cast<const float4*>(g);
    float4 gf = *reinterpret_cast<const float4*>(g + 256);
    float4 gg = *reinterpret_cast<const float4*>(g + 512);
    float4 go = *reinterpret_cast<const float4*>(g + 768);
    float4 c0 = *reinterpret_cast<const float4*>(cx_in + (size_t)b * 256 + j);
    float4 ho, co;
    co.x = sigmoidf_(gf.x) * c0.x + sigmoidf_(gi.x) * tanhf(gg.x); ho.x = sigmoidf_(go.x) * tanhf(co.x);
    co.y = sigmoidf_(gf.y) * c0.y + sigmoidf_(gi.y) * tanhf(gg.y); ho.y = sigmoidf_(go.y) * tanhf(co.y);
    co.z = sigmoidf_(gf.z) * c0.z + sigmoidf_(gi.z) * tanhf(gg.z); ho.z = sigmoidf_(go.z) * tanhf(co.z);
    co.w = sigmoidf_(gf.w) * c0.w + sigmoidf_(gi.w) * tanhf(gg.w); ho.w = sigmoidf_(go.w) * tanhf(co.w);
    size_t o = (size_t)b * 256 + j;
    *reinterpret_cast<float4*>(hx_out + o) = ho;
    *reinterpret_cast<float4*>(cx_out + o) = co;
    uint2 u = make_uint2(pack2h(__float2half(ho.x), __float2half(ho.y)),
                         pack2h(__float2half(ho.z), __float2half(ho.w)));
    *reinterpret_cast<uint2*>(hxo + o) = u;
}

// ---------------------------------------------------------------------------
// MMA / cp.async helpers
// ---------------------------------------------------------------------------
__device__ __forceinline__ void ldm4(uint32_t* r, uint32_t addr) {
    asm volatile("ldmatrix.sync.aligned.m8n8.x4.shared.b16 {%0,%1,%2,%3}, [%4];"
                 : "=r"(r[0]), "=r"(r[1]), "=r"(r[2]), "=r"(r[3]) : "r"(addr));
}
__device__ __forceinline__ void mma16816(float* c, const uint32_t* a, uint32_t b0, uint32_t b1) {
    asm volatile(
        "mma.sync.aligned.m16n8k16.row.col.f32.f16.f16.f32 "
        "{%0,%1,%2,%3}, {%4,%5,%6,%7}, {%8,%9}, {%0,%1,%2,%3};"
        : "+f"(c[0]), "+f"(c[1]), "+f"(c[2]), "+f"(c[3])
        : "r"(a[0]), "r"(a[1]), "r"(a[2]), "r"(a[3]), "r"(b0), "r"(b1));
}
#define CPA16(dst, src) asm volatile("cp.async.cg.shared.global [%0], [%1], 16;\n" :: "r"(dst), "l"(src))
#define CPCOMMIT()      asm volatile("cp.async.commit_group;\n")
#define CPWAIT1()       asm volatile("cp.async.wait_group 1;\n")
#define CPWAIT0()       asm volatile("cp.async.wait_group 0;\n")

// ---------------------------------------------------------------------------
// GEMM: C = epi( sum_seg A_seg @ W_seg^T ), fp16 single pass, fp32 acc.
// 256 threads, 8 warps (4m x 2n), BM=128, K64 chunks (144B rows), 3-stage
// cp.async ring, ONE __syncthreads per chunk. 2 CTAs/SM.
// K segments must be multiples of 64.
// EPI 0: +bias (split at nsplit into bias/bias2), relu if ACT
// EPI 1: +aux0[idxp[m]*1024+n]
// EPI 2: (+bias, relu) -> tanh(aux0[m*256+n]+v) * aux1[m*512+256+n]
// OUTM bit0: fp32 C; bit1: fp16 Ch.
// ---------------------------------------------------------------------------
template <int BN, int ACT, int EPI, int OUTM>
__global__ void __launch_bounds__(256, 2)
mma_gemm(int N,
         const __half* __restrict__ A0, int lda0,
         const __half* __restrict__ W0, int ldw0, int K0,
         const __half* __restrict__ A1, int lda1,
         const __half* __restrict__ W1, int ldw1, int K1,
         const float* __restrict__ bias, const float* __restrict__ bias2, int nsplit,
         const float* __restrict__ aux0, const float* __restrict__ aux1,
         const int* __restrict__ idxp,
         float* __restrict__ C, __half* __restrict__ Ch, int ldc) {
    constexpr int WN      = BN / 2;                 // warp n-extent (2 warps in n)
    constexpr int NT8     = WN / 8;
    constexpr int N16T    = WN / 16;
    constexpr int SSTR    = 72;                     // halves/row: 64 data + 8 pad (144B)
    constexpr int A_BYTES = 128 * SSTR * 2;         // 18432
    constexpr int W_BYTES = BN * SSTR * 2;
    constexpr int STAGEB  = A_BYTES + W_BYTES;
    constexpr int WIT     = BN / 32;                // W cp.async iters (slots = BN*8)

    extern __shared__ __half smem_dyn[];

    const int tid  = threadIdx.x;
    const int lane = tid & 31;
    const int wid  = tid >> 5;
    const int wm = wid & 3, wn = wid >> 2;          // 4 x 2 warps
    const int m0 = blockIdx.y * 128;
    const int n0 = blockIdx.x * BN;

    const uint32_t smb = (uint32_t)__cvta_generic_to_shared(smem_dyn);

    float acc[2][NT8][4];
    #pragma unroll
    for (int i = 0; i < 2; i++)
        #pragma unroll
        for (int j = 0; j < NT8; j++)
            #pragma unroll
            for (int q = 0; q < 4; q++) acc[i][j][q] = 0.f;

    const int nc0 = K0 >> 6;
    const int NC  = nc0 + (K1 >> 6);

    auto issue = [&](int c) {
        const __half *A, *W;
        int lda, ldw, kc;
        if (c < nc0) { A = A0; W = W0; lda = lda0; ldw = ldw0; kc = c << 6; }
        else         { A = A1; W = W1; lda = lda1; ldw = ldw1; kc = (c - nc0) << 6; }
        const uint32_t sb = smb + (uint32_t)(c % 3) * STAGEB;
        #pragma unroll
        for (int it = 0; it < 4; it++) {            // A: 128 rows x 8 segs
            int idx = tid + it * 256;
            int row = idx >> 3, seg = idx & 7;
            uint32_t off = (uint32_t)(row * SSTR + seg * 8) * 2;
            CPA16(sb + off, A + (size_t)(m0 + row) * lda + kc + seg * 8);
        }
        #pragma unroll
        for (int it = 0; it < WIT; it++) {          // W: BN rows x 8 segs
            int idx = tid + it * 256;
            int row = idx >> 3, seg = idx & 7;
            uint32_t off = (uint32_t)(row * SSTR + seg * 8) * 2;
            CPA16(sb + A_BYTES + off, W + (size_t)(n0 + row) * ldw + kc + seg * 8);
        }
    };

    issue(0); CPCOMMIT();
    if (NC > 1) { issue(1); CPCOMMIT(); }

    for (int c = 0; c < NC; c++) {
        if (c + 1 < NC) CPWAIT1(); else CPWAIT0();  // stage c landed
        __syncthreads();                            // also: all warps done with c-1
        if (c + 2 < NC) { issue(c + 2); CPCOMMIT(); }  // overwrites stage of c-1: safe

        const uint32_t sb = smb + (uint32_t)(c % 3) * STAGEB;
        const uint32_t bA = sb;
        const uint32_t bW = sb + A_BYTES;

        #pragma unroll
        for (int kk = 0; kk < 64; kk += 16) {
            const int col = kk + ((lane >> 4) << 3);
            uint32_t a0[4], a1[4];
            {
                int row = wm * 32 + (lane & 15);
                ldm4(a0, bA + (uint32_t)(row * SSTR + col) * 2u);
                ldm4(a1, bA + (uint32_t)((row + 16) * SSTR + col) * 2u);
            }
            #pragma unroll
            for (int t = 0; t < N16T; t++) {
                uint32_t bh[4];
                int row = wn * WN + t * 16 + (lane & 15);
                ldm4(bh, bW + (uint32_t)(row * SSTR + col) * 2u);
                #pragma unroll
                for (int hs = 0; hs < 2; hs++) {
                    int nt = 2 * t + hs;
                    mma16816(acc[0][nt], a0, bh[hs], bh[2 + hs]);
                    mma16816(acc[1][nt], a1, bh[hs], bh[2 + hs]);
                }
            }
        }
    }

    // epilogue
    #pragma unroll
    for (int mt = 0; mt < 2; mt++) {
        int r0 = m0 + wm * 32 + mt * 16 + (lane >> 2);
        int r1 = r0 + 8;
        int ib0 = 0, ib1 = 0;
        if (EPI == 1) { ib0 = idxp[r0]; ib1 = idxp[r1]; }
        #pragma unroll
        for (int nt = 0; nt < NT8; nt++) {
            int cc = n0 + wn * WN + nt * 8 + ((lane & 3) << 1);
            if (cc < N) {
                float bb0 = 0.f, bb1 = 0.f;
                if (EPI != 1 && bias) {
                    if (cc < nsplit) { bb0 = bias[cc]; bb1 = bias[cc + 1]; }
                    else             { bb0 = bias2[cc - nsplit]; bb1 = bias2[cc + 1 - nsplit]; }
                }
                #pragma unroll
                for (int p = 0; p < 2; p++) {
                    int r  = p ? r1 : r0;
                    int ib = p ? ib1 : ib0;
                    float x = acc[mt][nt][2 * p];
                    float y = acc[mt][nt][2 * p + 1];
                    if (EPI == 1) {
                        x += aux0[(size_t)ib * 1024 + cc];
                        y += aux0[(size_t)ib * 1024 + cc + 1];
                    } else {
                        x += bb0; y += bb1;
                    }
                    if (ACT) { x = fmaxf(x, 0.f); y = fmaxf(y, 0.f); }
                    if (EPI == 2) {
                        x = tanhf(aux0[(size_t)r * 256 + cc] + x)     * aux1[(size_t)r * 512 + 256 + cc];
                        y = tanhf(aux0[(size_t)r * 256 + cc + 1] + y) * aux1[(size_t)r * 512 + 256 + cc + 1];
                    }
                    size_t o = (size_t)r * ldc + cc;
                    if (OUTM & 1)
                        *reinterpret_cast<float2*>(&C[o]) = make_float2(x, y);
                    if (OUTM & 2)
                        *reinterpret_cast<uint32_t*>(Ch + o) = pack2h(__float2half(x), __float2half(y));
                }
            }
        }
    }
}

// ---------------------------------------------------------------------------
// Final heads: pv2 [B,96] = pol2(0:64) | val2(64:96)
// ---------------------------------------------------------------------------
__global__ void k_heads(const float* __restrict__ pv2,
                        const float* __restrict__ w_p, const float* __restrict__ b_p,
                        const float* __restrict__ w_v, const float* __restrict__ b_v,
                        float* __restrict__ out_val, float* __restrict__ out_pol) {
    __shared__ float sp[64][97];
    int r0 = blockIdx.x * 64;
    for (int i = threadIdx.x; i < 64 * 96; i += blockDim.x) {
        int r = i / 96, c = i - r * 96;
        sp[r][c] = pv2[(size_t)(r0 + r) * 96 + c];
    }
    __syncthreads();
    int t = threadIdx.x;
    if (t < 64) {
        int b = r0 + t;
        float p0 = b_p[0], p1 = b_p[1], p2 = b_p[2];
        #pragma unroll
        for (int k = 0; k < 64; k++) {
            float x = sp[t][k];
            p0 = fmaf(x, w_p[k], p0);
            p1 = fmaf(x, w_p[64 + k], p1);
            p2 = fmaf(x, w_p[128 + k], p2);
        }
        out_pol[(size_t)b * 3 + 0] = p0;
        out_pol[(size_t)b * 3 + 1] = p1;
        out_pol[(size_t)b * 3 + 2] = p2;
        float v = b_v[0];
        #pragma unroll
        for (int k = 0; k < 32; k++) v = fmaf(sp[t][64 + k], w_v[k], v);
        out_val[b] = v;
    }
}

// ---------------------------------------------------------------------------
// host launcher
// ---------------------------------------------------------------------------
extern "C" void kernel_launch(void* const* d_in, const int* in_sizes, int n_in,
                              void* d_out, int out_size) {
    const float* img   = (const float*)d_in[0];
    const int*   idx   = (const int*)  d_in[1];
    const float* hx_in = (const float*)d_in[2];
    const float* cx_in = (const float*)d_in[3];
    const float* query = (const float*)d_in[4];
    const float* emb   = (const float*)d_in[5];
    const float* w_ta  = (const float*)d_in[6];
    const float* b_ta  = (const float*)d_in[7];
    const float* w_ih  = (const float*)d_in[8];
    const float* w_hh  = (const float*)d_in[9];
    const float* b_ih  = (const float*)d_in[10];
    const float* b_hh  = (const float*)d_in[11];
    const float* w_q   = (const float*)d_in[12];
    const float* b_q   = (const float*)d_in[13];
    const float* w_k   = (const float*)d_in[14];
    const float* b_k   = (const float*)d_in[15];
    const float* w_ba  = (const float*)d_in[16];
    const float* b_ba  = (const float*)d_in[17];
    const float* w_at  = (const float*)d_in[18];
    const float* b_at  = (const float*)d_in[19];
    const float* w_p1  = (const float*)d_in[20];
    const float* b_p1  = (const float*)d_in[21];
    const float* w_p2  = (const float*)d_in[22];
    const float* b_p2  = (const float*)d_in[23];
    const float* w_p   = (const float*)d_in[24];
    const float* b_p   = (const float*)d_in[25];
    const float* w_v1  = (const float*)d_in[26];
    const float* b_v1  = (const float*)d_in[27];
    const float* w_v2  = (const float*)d_in[28];
    const float* b_v2  = (const float*)d_in[29];
    const float* w_v   = (const float*)d_in[30];
    const float* b_v   = (const float*)d_in[31];

    const int B = in_sizes[0] / 256;  // 32768

    float* F = nullptr;
    cudaGetSymbolAddress((void**)&F, g_f32);
    __half* HF = nullptr;
    cudaGetSymbolAddress((void**)&HF, g_hf);

    float* tab   = F + F_TAB;
    float* pre2  = F + F_PRE2;
    float* gates = F + F_GATES;
    float* mlpf  = F + F_MLP;
    float* qout  = F + F_QOUT;
    float* pv2   = F + F_PV2;

    float* out   = (float*)d_out;
    float* o_val = out;
    float* o_pol = out + (size_t)B;
    float* o_hx  = out + (size_t)B * 4;
    float* o_cx  = o_hx + (size_t)B * 256;

    // smem: 3 stages; stage = 18432 + BN*144
    const int SM128 = 3 * (18432 + 128 * 144);  // 110592
    const int SM64  = 3 * (18432 + 64 * 144);   // 82944
    cudaFuncSetAttribute(mma_gemm<128, 0, 1, 1>, cudaFuncAttributeMaxDynamicSharedMemorySize, SM128);
    cudaFuncSetAttribute(mma_gemm<128, 1, 0, 1>, cudaFuncAttributeMaxDynamicSharedMemorySize, SM128);
    cudaFuncSetAttribute(mma_gemm<128, 1, 0, 3>, cudaFuncAttributeMaxDynamicSharedMemorySize, SM128);
    cudaFuncSetAttribute(mma_gemm<128, 1, 2, 2>, cudaFuncAttributeMaxDynamicSharedMemorySize, SM128);
    cudaFuncSetAttribute(mma_gemm<128, 1, 0, 2>, cudaFuncAttributeMaxDynamicSharedMemorySize, SM128);
    cudaFuncSetAttribute(mma_gemm<64, 1, 0, 2>,  cudaFuncAttributeMaxDynamicSharedMemorySize, SM64);
    cudaFuncSetAttribute(mma_gemm<64, 1, 0, 1>,  cudaFuncAttributeMaxDynamicSharedMemorySize, SM64);

    // K0: tables
    k0_tables<<<1, 1024>>>(emb, w_ta, b_ta, w_ih, b_ih, b_hh, tab, pre2);

    // fused weight convert (9 segments, one launch)
    {
        WAll d;
        auto seg = [&](int i, const float* src, int srcld, int cols, int rows, int padrows,
                       size_t hoff) {
            d.s[i] = WSeg{src, nullptr, srcld, cols, rows, padrows * cols, 0, (long long)hoff};
        };
        seg(0, w_ih, 512, 256, 1024, 1024, H_WIH);
        seg(1, w_hh, 256, 256, 1024, 1024, H_WHH);
        seg(2, w_ba, 512, 512, 512, 512, H_WBA);
        seg(3, w_q,  256, 256, 256, 256, H_WQ);
        seg(4, w_k,  256, 256, 256, 256, H_WK);
        seg(5, w_at, 512, 512, 256, 256, H_WAT);
        seg(6, w_p1, 256, 256, 128, 128, H_WPV);
        seg(7, w_v1, 256, 256, 64, 64, H_WPV + 128 * 256);
        d.s[8] = WSeg{w_p2, w_v2, 0, 0, 0, 128 * 192, 2, (long long)H_WC};
        int total = 0;
        for (int i = 0; i < 9; i++) total += d.s[i].total;
        k_wsplit_all<<<(total + 255) / 256, 256>>>(d, HF);
    }

    // fused prep
    k_prep<<<(3 * B * 64 + 255) / 256, 256>>>(
        (const float4*)img, idx, tab, (const float4*)hx_in, (const float4*)query,
        HF + H_FUS, HF + H_HXI, HF + H_QRY, B * 64);

    // K2: gates = fus @ w_ih[:,:256]^T + hx @ w_hh^T + pre2[idx]
    mma_gemm<128, 0, 1, 1><<<dim3(8, B / 128), 256, SM128>>>(
        1024,
        HF + H_FUS, 256, HF + H_WIH, 256, 256,
        HF + H_HXI, 256, HF + H_WHH, 256, 256,
        nullptr, nullptr, 1 << 30, pre2, nullptr, idx, gates, nullptr, 1024);

    // K3: LSTM
    k_lstm<<<(B * 64 + 255) / 256, 256>>>(gates, cx_in, o_hx, o_cx, HF + H_HXO, B * 64);

    // K5: qout = relu(query @ w_q^T + b_q)  (fp32)
    mma_gemm<128, 1, 0, 1><<<dim3(2, B / 128), 256, SM128>>>(
        256,
        HF + H_QRY, 256, HF + H_WQ, 256, 256,
        nullptr, 0, nullptr, 0, 0,
        b_q, nullptr, 1 << 30, nullptr, nullptr, nullptr, qout, nullptr, 256);

    // K4: mlp = relu([fus|hx] @ w_ba^T + b_ba)  (fp32 + fp16)
    mma_gemm<128, 1, 0, 3><<<dim3(4, B / 128), 256, SM128>>>(
        512,
        HF + H_FUS, 256, HF + H_WBA, 512, 256,
        HF + H_HXO, 256, HF + H_WBA + 256, 512, 256,
        b_ba, nullptr, 1 << 30, nullptr, nullptr, nullptr, mlpf, HF + H_MLP, 512);

    // K6: avec = tanh(qout + relu(key @ w_k^T + b_k)) * val  (fp16)
    mma_gemm<128, 1, 2, 2><<<dim3(2, B / 128), 256, SM128>>>(
        256,
        HF + H_MLP, 512, HF + H_WK, 256, 256,
        nullptr, 0, nullptr, 0, 0,
        b_k, nullptr, 1 << 30, qout, mlpf, nullptr, nullptr, HF + H_AVEC, 256);

    // K7: attnw = relu([avec|hx] @ w_at^T + b_at)  (fp16)
    mma_gemm<128, 1, 0, 2><<<dim3(2, B / 128), 256, SM128>>>(
        256,
        HF + H_AVEC, 256, HF + H_WAT, 512, 256,
        HF + H_HXO, 256, HF + H_WAT + 256, 512, 256,
        b_at, nullptr, 1 << 30, nullptr, nullptr, nullptr, nullptr, HF + H_ATT, 256);

    // K8: [pol1|val1] = relu(attnw @ [w_p1;w_v1]^T + [b_p1;b_v1])  N=192 (fp16)
    mma_gemm<64, 1, 0, 2><<<dim3(3, B / 128), 256, SM64>>>(
        192,
        HF + H_ATT, 256, HF + H_WPV, 256, 256,
        nullptr, 0, nullptr, 0, 0,
        b_p1, b_v1, 128, nullptr, nullptr, nullptr, nullptr, HF + H_P1V1, 192);

    // K9: [pol2|val2] = relu([pol1|val1] @ blockdiag(w_p2,w_v2)^T + [b_p2;b_v2])  N=96 (fp32)
    mma_gemm<64, 1, 0, 1><<<dim3(2, B / 128), 256, SM64>>>(
        96,
        HF + H_P1V1, 192, HF + H_WC, 192, 192,
        nullptr, 0, nullptr, 0, 0,
        b_p2, b_v2, 64, nullptr, nullptr, nullptr, pv2, nullptr, 96);

    // K10: heads
    k_heads<<<B / 64, 256>>>(pv2, w_p, b_p, w_v, b_v, o_val, o_pol);
}